// round 1
// baseline (speedup 1.0000x reference)
#include <cuda_runtime.h>
#include <math.h>

#define NN 100000
#define EE 1000000
#define GG 5000
#define HH 64
#define SLOPEF 0.01f

// ---------------- scratch (device globals; no allocation allowed) ----------------
__device__ float    g_x[NN*HH];
__device__ float    g_xl1[NN*HH];
__device__ float    g_h[NN*HH];
__device__ float    g_p[NN*HH];
__device__ float    g_mixed[NN*HH];
__device__ float    g_xj[EE*HH];          // 256 MB
__device__ float    g_score[EE];
__device__ unsigned g_m[NN];
__device__ float    g_denom[NN];
__device__ float    g_ai[NN];
__device__ float    g_an[NN];
__device__ float    g_gout[GG*HH];
__device__ float    g_hg[GG*HH];

__device__ __forceinline__ float leaky(float v){ return v > 0.f ? v : SLOPEF * v; }
// order-preserving float<->uint for atomicMax-based segment max
__device__ __forceinline__ unsigned encf(float f){
    unsigned b = __float_as_uint(f);
    return (b & 0x80000000u) ? ~b : (b | 0x80000000u);
}
__device__ __forceinline__ float decf(unsigned k){
    if (k == 0u) return 0.f;   // empty segment -> reference replaces -inf with 0
    return __uint_as_float((k & 0x80000000u) ? (k & 0x7FFFFFFFu) : ~k);
}

// ---------------- generic node GEMM: out[n,k] = act(in[n,:]·W[k,:] + b[k]) ----------------
// W row stride ldW (input dim is always 64). act: 0=none, 1=leaky
__global__ void k_gemm(float* __restrict__ out, const float* __restrict__ in,
                       const float* __restrict__ W, int ldW,
                       const float* __restrict__ bias, int nrows, int act)
{
    __shared__ float Wt[64*65];    // [d][k] transposed, padded
    __shared__ float ins[32*64];
    int tx = threadIdx.x;
    for (int i = tx; i < 4096; i += 256){ int k = i >> 6, d = i & 63; Wt[d*65+k] = W[k*ldW + d]; }
    int base = blockIdx.x * 32;
    int nr = min(32, nrows - base);
    for (int i = tx; i < nr*64; i += 256) ins[i] = in[base*64 + i];
    __syncthreads();
    int k = tx & 63, slot = tx >> 6;
    float acc[8];
    #pragma unroll
    for (int j = 0; j < 8; j++) acc[j] = 0.f;
    for (int d = 0; d < 64; d++){
        float w = Wt[d*65 + k];
        #pragma unroll
        for (int j = 0; j < 8; j++) acc[j] += ins[(slot + 4*j)*64 + d] * w;
    }
    float b = bias ? bias[k] : 0.f;
    #pragma unroll
    for (int j = 0; j < 8; j++){
        int r = base + slot + 4*j;
        if (r < nrows){
            float v = acc[j] + b;
            if (act == 1) v = leaky(v);
            out[r*64 + k] = v;
        }
    }
}

// ---------------- per-row dot(s) with 64-vector(s) ----------------
__global__ void k_dot2(float* __restrict__ o1, const float* __restrict__ w1,
                       float* __restrict__ o2, const float* __restrict__ w2,
                       const float* __restrict__ in, int nrows)
{
    int wid  = (blockIdx.x*blockDim.x + threadIdx.x) >> 5;
    int lane = threadIdx.x & 31;
    int nw   = (gridDim.x*blockDim.x) >> 5;
    for (int r = wid; r < nrows; r += nw){
        float v1 = in[r*64 + lane], v2 = in[r*64 + lane + 32];
        float s1 = v1*__ldg(w1+lane) + v2*__ldg(w1+lane+32);
        float s2 = 0.f;
        if (o2) s2 = v1*__ldg(w2+lane) + v2*__ldg(w2+lane+32);
        #pragma unroll
        for (int o = 16; o > 0; o >>= 1){
            s1 += __shfl_xor_sync(0xffffffffu, s1, o);
            s2 += __shfl_xor_sync(0xffffffffu, s2, o);
        }
        if (lane == 0){ o1[r] = s1; if (o2) o2[r] = s2; }
    }
}

// ---------------- GATEConv edge pass 1: xj + score + segmax ----------------
// p[n,64] = raw@W_raw.T + gate_nl_b (bias pre-added). si[n] = x[n]·a_i.
__global__ void k_gate_edge1(const int* __restrict__ ei, const float* __restrict__ eattr,
                             const float* __restrict__ p, const float* __restrict__ si,
                             const float* __restrict__ gate_nl_w,
                             const float* __restrict__ align_w,
                             const float* __restrict__ align_b,
                             float* __restrict__ xj, float* __restrict__ score,
                             unsigned* __restrict__ mbuf)
{
    __shared__ float WeT[16*65];   // edge-attr part of gate_nl_w, transposed [d][k]
    __shared__ float aj[64];
    int tx = threadIdx.x;
    for (int i = tx; i < 1024; i += blockDim.x){ int k = i >> 4, d = i & 15; WeT[d*65+k] = gate_nl_w[k*80 + 64 + d]; }
    for (int i = tx; i < 64; i += blockDim.x) aj[i] = align_w[64 + i];
    __syncthreads();
    float ab = __ldg(align_b);
    int lane = tx & 31;
    int wid  = (blockIdx.x*blockDim.x + tx) >> 5;
    int nw   = (gridDim.x*blockDim.x) >> 5;
    for (int e = wid; e < EE; e += nw){
        int s = ei[e], t = ei[EE + e];
        float ea = (lane < 16) ? eattr[e*16 + lane] : 0.f;
        float x1 = p[s*64 + lane];
        float x2 = p[s*64 + lane + 32];
        #pragma unroll
        for (int d = 0; d < 16; d++){
            float ed = __shfl_sync(0xffffffffu, ea, d);
            x1 += ed * WeT[d*65 + lane];
            x2 += ed * WeT[d*65 + lane + 32];
        }
        x1 = leaky(x1); x2 = leaky(x2);
        xj[e*64 + lane] = x1; xj[e*64 + lane + 32] = x2;
        float part = x1*aj[lane] + x2*aj[lane + 32];
        #pragma unroll
        for (int o = 16; o > 0; o >>= 1) part += __shfl_xor_sync(0xffffffffu, part, o);
        if (lane == 0){
            float sc = leaky(si[t] + part + ab);
            score[e] = sc;
            atomicMax(mbuf + t, encf(sc));
        }
    }
}

// ---------------- segment softmax denominator (edges: idx=dst; nodes: idx=batch) ----------------
__global__ void k_seg_denom(const float* __restrict__ score, const int* __restrict__ idx,
                            const unsigned* __restrict__ mbuf, float* __restrict__ denom, int n)
{
    int i  = blockIdx.x*blockDim.x + threadIdx.x;
    int st = gridDim.x*blockDim.x;
    for (; i < n; i += st){
        int t = idx[i];
        atomicAdd(denom + t, expf(score[i] - decf(mbuf[t])));
    }
}

// ---------------- GATEConv edge pass 3: msg = (xj@Watt.T + b)*aw, scatter to dst ----------------
__global__ void k_gate_edge3(const int* __restrict__ ei, const float* __restrict__ xj,
                             const float* __restrict__ score,
                             const unsigned* __restrict__ mbuf, const float* __restrict__ denom,
                             const float* __restrict__ attend_w, const float* __restrict__ attend_b,
                             float* __restrict__ hout)
{
    __shared__ float Wt[64*65];
    __shared__ float bb[64];
    int tx = threadIdx.x;
    for (int i = tx; i < 4096; i += blockDim.x){ int k = i >> 6, d = i & 63; Wt[d*65+k] = attend_w[k*64 + d]; }
    for (int i = tx; i < 64; i += blockDim.x) bb[i] = attend_b[i];
    __syncthreads();
    int lane = tx & 31;
    int wid  = (blockIdx.x*blockDim.x + tx) >> 5;
    int nw   = (gridDim.x*blockDim.x) >> 5;
    for (int e = wid; e < EE; e += nw){
        int t = ei[EE + e];
        float x1 = xj[e*64 + lane], x2 = xj[e*64 + lane + 32];
        float m1 = bb[lane], m2 = bb[lane + 32];
        #pragma unroll
        for (int d = 0; d < 32; d++){
            float xd = __shfl_sync(0xffffffffu, x1, d);
            m1 += xd * Wt[d*65 + lane];
            m2 += xd * Wt[d*65 + lane + 32];
        }
        #pragma unroll
        for (int d = 0; d < 32; d++){
            float xd = __shfl_sync(0xffffffffu, x2, d);
            m1 += xd * Wt[(d+32)*65 + lane];
            m2 += xd * Wt[(d+32)*65 + lane + 32];
        }
        float aw = expf(score[e] - decf(mbuf[t])) / (denom[t] + 1e-16f);
        atomicAdd(hout + t*64 + lane,      m1 * aw);
        atomicAdd(hout + t*64 + lane + 32, m2 * aw);
    }
}

// ---------------- factored attention score: s = leaky(ai[seg] + an[g]) ----------------
__global__ void k_scoreA(const float* __restrict__ ai, const float* __restrict__ an,
                         const int* __restrict__ seg, const int* __restrict__ gidx,
                         const float* __restrict__ bptr,
                         float* __restrict__ score, unsigned* __restrict__ mbuf, int n)
{
    float b = __ldg(bptr);
    int i  = blockIdx.x*blockDim.x + threadIdx.x;
    int st = gridDim.x*blockDim.x;
    for (; i < n; i += st){
        int t = seg[i];
        int g = gidx ? gidx[i] : i;
        float sc = leaky(ai[t] + an[g] + b);
        score[i] = sc;
        atomicMax(mbuf + t, encf(sc));
    }
}

// ---------------- scatter: out[seg[i]] += vecs[g]*aw ----------------
__global__ void k_scatter_aw(const float* __restrict__ vecs, const int* __restrict__ gidx,
                             const int* __restrict__ seg,
                             const float* __restrict__ score, const unsigned* __restrict__ mbuf,
                             const float* __restrict__ denom, float* __restrict__ outbuf, int n)
{
    int lane = threadIdx.x & 31;
    int wid  = (blockIdx.x*blockDim.x + threadIdx.x) >> 5;
    int nw   = (gridDim.x*blockDim.x) >> 5;
    for (int i = wid; i < n; i += nw){
        int t = seg[i];
        float aw = expf(score[i] - decf(mbuf[t])) / (denom[t] + 1e-16f);
        int g = gidx ? gidx[i] : i;
        atomicAdd(outbuf + t*64 + lane,      vecs[g*64 + lane]      * aw);
        atomicAdd(outbuf + t*64 + lane + 32, vecs[g*64 + lane + 32] * aw);
    }
}

// ---------------- GRU cell: xout = relu(gru(elu?(hin), xprev)) ----------------
// gi = h@wih.T + bih ; gh = x@whh.T + bhh ; r,z,n gates; out = (1-z)*n + z*x
__global__ void k_gru(float* __restrict__ xout, const float* __restrict__ hin,
                      const float* __restrict__ xprev,
                      const float* __restrict__ wih, const float* __restrict__ whh,
                      const float* __restrict__ bih, const float* __restrict__ bhh,
                      int nrows, int elu_in)
{
    extern __shared__ float sm[];
    float* wt = sm;                 // [64][193] transposed wih
    float* ut = sm + 64*193;        // [64][193] transposed whh
    float* hs = ut + 64*193;        // [32][64]
    float* xs = hs + 32*64;         // [32][64]
    int tx = threadIdx.x;
    for (int i = tx; i < 12288; i += 256){
        int r = i >> 6, d = i & 63;
        wt[d*193 + r] = wih[i];
        ut[d*193 + r] = whh[i];
    }
    int base = blockIdx.x * 32;
    int nr = min(32, nrows - base);
    for (int i = tx; i < 32*64; i += 256){
        if (i < nr*64){
            float v = hin[base*64 + i];
            if (elu_in) v = v > 0.f ? v : expm1f(v);
            hs[i] = v;
            xs[i] = xprev[base*64 + i];
        } else { hs[i] = 0.f; xs[i] = 0.f; }
    }
    __syncthreads();
    int k = tx & 63, slot = tx >> 6;
    float a[8][6];
    #pragma unroll
    for (int j = 0; j < 8; j++)
        #pragma unroll
        for (int q = 0; q < 6; q++) a[j][q] = 0.f;
    for (int d = 0; d < 64; d++){
        float w0 = wt[d*193 + k], w1 = wt[d*193 + 64 + k], w2 = wt[d*193 + 128 + k];
        float u0 = ut[d*193 + k], u1 = ut[d*193 + 64 + k], u2 = ut[d*193 + 128 + k];
        #pragma unroll
        for (int j = 0; j < 8; j++){
            float hv = hs[(slot + 4*j)*64 + d];
            float xv = xs[(slot + 4*j)*64 + d];
            a[j][0] += hv*w0; a[j][1] += hv*w1; a[j][2] += hv*w2;
            a[j][3] += xv*u0; a[j][4] += xv*u1; a[j][5] += xv*u2;
        }
    }
    float br = bih[k], bz = bih[64 + k], bn = bih[128 + k];
    float cr = bhh[k], cz = bhh[64 + k], cn = bhh[128 + k];
    #pragma unroll
    for (int j = 0; j < 8; j++){
        int r0 = slot + 4*j;
        int row = base + r0;
        if (row < nrows){
            float gir = a[j][0] + br, giz = a[j][1] + bz, gin = a[j][2] + bn;
            float ghr = a[j][3] + cr, ghz = a[j][4] + cz, ghn = a[j][5] + cn;
            float rr = 1.f / (1.f + expf(-(gir + ghr)));
            float zz = 1.f / (1.f + expf(-(giz + ghz)));
            float nn2 = tanhf(gin + rr*ghn);
            float xp = xs[r0*64 + k];
            float v = (1.f - zz)*nn2 + zz*xp;
            xout[row*64 + k] = fmaxf(v, 0.f);
        }
    }
}

// ---------------- misc ----------------
__global__ void k_segsum(const float* __restrict__ x, const int* __restrict__ batch,
                         float* __restrict__ gout)
{
    int lane = threadIdx.x & 31;
    int wid  = (blockIdx.x*blockDim.x + threadIdx.x) >> 5;
    int nw   = (gridDim.x*blockDim.x) >> 5;
    for (int n = wid; n < NN; n += nw){
        int g = batch[n];
        atomicAdd(gout + g*64 + lane,      x[n*64 + lane]);
        atomicAdd(gout + g*64 + lane + 32, x[n*64 + lane + 32]);
    }
}

__global__ void k_relu(float* __restrict__ v, int n)
{
    int i = blockIdx.x*blockDim.x + threadIdx.x;
    int st = gridDim.x*blockDim.x;
    for (; i < n; i += st) v[i] = fmaxf(v[i], 0.f);
}

__global__ void k_mix(float* __restrict__ o, const float* __restrict__ a,
                      const float* __restrict__ b, int n)
{
    int i = blockIdx.x*blockDim.x + threadIdx.x;
    int st = gridDim.x*blockDim.x;
    for (; i < n; i += st) o[i] = 0.5f * (a[i] + b[i]);
}

__global__ void k_final(const float* __restrict__ gout, const float* __restrict__ w,
                        const float* __restrict__ b, float* __restrict__ out, int n)
{
    int wid  = (blockIdx.x*blockDim.x + threadIdx.x) >> 5;
    int lane = threadIdx.x & 31;
    if (wid >= n) return;
    float s = gout[wid*64 + lane]*__ldg(w + lane) + gout[wid*64 + lane + 32]*__ldg(w + lane + 32);
    #pragma unroll
    for (int o = 16; o > 0; o >>= 1) s += __shfl_xor_sync(0xffffffffu, s, o);
    if (lane == 0) out[wid] = s + __ldg(b);
}

// =====================================================================
extern "C" void kernel_launch(void* const* d_in, const int* in_sizes, int n_in,
                              void* d_out_, int out_size)
{
    const float* raw           = (const float*)d_in[0];
    const int*   ei            = (const int*)  d_in[1];
    const float* eattr         = (const float*)d_in[2];
    const int*   batch         = (const int*)  d_in[3];
    const float* lin1_w        = (const float*)d_in[4];
    const float* lin1_b        = (const float*)d_in[5];
    const float* gate_nl_w     = (const float*)d_in[6];
    const float* gate_nl_b     = (const float*)d_in[7];
    const float* gate_align_w  = (const float*)d_in[8];
    const float* gate_align_b  = (const float*)d_in[9];
    const float* gate_attend_w = (const float*)d_in[10];
    const float* gate_attend_b = (const float*)d_in[11];
    const float* conv_align_w  = (const float*)d_in[12];
    const float* conv_align_b  = (const float*)d_in[13];
    const float* conv_attend_w = (const float*)d_in[14];
    const float* conv_attend_b = (const float*)d_in[15];
    const float* agru_wih      = (const float*)d_in[16];
    const float* agru_whh      = (const float*)d_in[17];
    const float* agru_bih      = (const float*)d_in[18];
    const float* agru_bhh      = (const float*)d_in[19];
    const float* mol_align_w   = (const float*)d_in[20];
    const float* mol_align_b   = (const float*)d_in[21];
    const float* mol_attend_w  = (const float*)d_in[22];
    const float* mol_attend_b  = (const float*)d_in[23];
    const float* mgru_wih      = (const float*)d_in[24];
    const float* mgru_whh      = (const float*)d_in[25];
    const float* mgru_bih      = (const float*)d_in[26];
    const float* mgru_bhh      = (const float*)d_in[27];
    const float* lin2_w        = (const float*)d_in[28];
    const float* lin2_b        = (const float*)d_in[29];
    float* outp = (float*)d_out_;

    float *px, *pxl1, *ph, *pp, *pmixed, *pxj, *pscore, *pdenom, *pai, *pan, *pgout, *phg;
    unsigned* pm;
    cudaGetSymbolAddress((void**)&px,     g_x);
    cudaGetSymbolAddress((void**)&pxl1,   g_xl1);
    cudaGetSymbolAddress((void**)&ph,     g_h);
    cudaGetSymbolAddress((void**)&pp,     g_p);
    cudaGetSymbolAddress((void**)&pmixed, g_mixed);
    cudaGetSymbolAddress((void**)&pxj,    g_xj);
    cudaGetSymbolAddress((void**)&pscore, g_score);
    cudaGetSymbolAddress((void**)&pm,     g_m);
    cudaGetSymbolAddress((void**)&pdenom, g_denom);
    cudaGetSymbolAddress((void**)&pai,    g_ai);
    cudaGetSymbolAddress((void**)&pan,    g_an);
    cudaGetSymbolAddress((void**)&pgout,  g_gout);
    cudaGetSymbolAddress((void**)&phg,    g_hg);

    const int GRU_SMEM = (2*64*193 + 2*32*64) * 4;   // 115200 bytes
    cudaFuncSetAttribute(k_gru, cudaFuncAttributeMaxDynamicSharedMemorySize, GRU_SMEM);

    const int GBN = (NN + 31) / 32;   // node-gemm / gru grid
    const int GBG = (GG + 31) / 32;

    // ---- input projection + GATEConv precompute ----
    k_gemm<<<GBN, 256>>>(px, raw, lin1_w, 64, lin1_b, NN, 1);           // x = leaky(raw@lin1.T + b)
    k_gemm<<<GBN, 256>>>(pp, raw, gate_nl_w, 80, gate_nl_b, NN, 0);     // p = raw@W_raw.T + b_nl
    k_dot2<<<512, 256>>>(pai, gate_align_w, nullptr, nullptr, px, NN);  // si = x·a_i

    // ---- GATEConv ----
    cudaMemsetAsync(pm,     0, NN * sizeof(unsigned));
    cudaMemsetAsync(pdenom, 0, NN * sizeof(float));
    cudaMemsetAsync(ph,     0, NN * HH * sizeof(float));
    k_gate_edge1<<<2048, 256>>>(ei, eattr, pp, pai, gate_nl_w, gate_align_w, gate_align_b,
                                pxj, pscore, pm);
    k_seg_denom<<<2048, 256>>>(pscore, ei + EE, pm, pdenom, EE);
    k_gate_edge3<<<2048, 256>>>(ei, pxj, pscore, pm, pdenom, gate_attend_w, gate_attend_b, ph);
    k_gru<<<GBN, 256, GRU_SMEM>>>(px, ph, px, agru_wih, agru_whh, agru_bih, agru_bhh, NN, 1);

    // ---- 2x GATConv (factored attention) ----
    for (int l = 0; l < 2; l++){
        k_gemm<<<GBN, 256>>>(pp, px, conv_attend_w + l*64*64, 64, conv_attend_b + l*64, NN, 0);
        k_dot2<<<512, 256>>>(pai, conv_align_w + l*128, pan, conv_align_w + l*128 + 64, px, NN);
        cudaMemsetAsync(pm,     0, NN * sizeof(unsigned));
        cudaMemsetAsync(pdenom, 0, NN * sizeof(float));
        cudaMemsetAsync(ph,     0, NN * HH * sizeof(float));
        k_scoreA<<<2048, 256>>>(pai, pan, ei + EE, ei, conv_align_b + l, pscore, pm, EE);
        k_seg_denom<<<2048, 256>>>(pscore, ei + EE, pm, pdenom, EE);
        k_scatter_aw<<<2048, 256>>>(pp, ei, ei + EE, pscore, pm, pdenom, ph, EE);
        k_gru<<<GBN, 256, GRU_SMEM>>>(px, ph, px,
                                      agru_wih + (l+1)*192*64, agru_whh + (l+1)*192*64,
                                      agru_bih + (l+1)*192,    agru_bhh + (l+1)*192, NN, 1);
        if (l == 0)
            cudaMemcpyAsync(pxl1, px, NN * HH * sizeof(float), cudaMemcpyDeviceToDevice);
    }

    // ---- molecule readout ----
    cudaMemsetAsync(pgout, 0, GG * HH * sizeof(float));
    k_segsum<<<1024, 256>>>(px, batch, pgout);
    k_relu<<<256, 256>>>(pgout, GG * HH);

    for (int t = 0; t < 2; t++){
        const float* mixptr;
        if (t == 0){ k_mix<<<2048, 256>>>(pmixed, px, pxl1, NN * HH); mixptr = pmixed; }
        else       { mixptr = px; }   // cached[-1] == x  => 0.5*(x+x) == x
        k_gemm<<<GBN, 256>>>(pp, mixptr, mol_attend_w, 64, mol_attend_b, NN, 0);   // z
        k_dot2<<<512, 256>>>(pan, mol_align_w + 64, nullptr, nullptr, mixptr, NN);
        k_dot2<<<64,  256>>>(pai, mol_align_w,      nullptr, nullptr, pgout, GG);
        cudaMemsetAsync(pm,     0, GG * sizeof(unsigned));
        cudaMemsetAsync(pdenom, 0, GG * sizeof(float));
        cudaMemsetAsync(phg,    0, GG * HH * sizeof(float));
        k_scoreA<<<512, 256>>>(pai, pan, batch, nullptr, mol_align_b, pscore, pm, NN);
        k_seg_denom<<<512, 256>>>(pscore, batch, pm, pdenom, NN);
        k_scatter_aw<<<1024, 256>>>(pp, nullptr, batch, pscore, pm, pdenom, phg, NN);
        k_gru<<<GBG, 256, GRU_SMEM>>>(pgout, phg, pgout, mgru_wih, mgru_whh, mgru_bih, mgru_bhh, GG, 1);
    }

    k_final<<<(GG*32 + 255)/256, 256>>>(pgout, lin2_w, lin2_b, outp, GG);
}

// round 2
// speedup vs baseline: 1.5753x; 1.5753x over previous
#include <cuda_runtime.h>
#include <math.h>

#define NN 100000
#define EE 1000000
#define GG 5000
#define SLOPEF 0.01f

// ---------------- scratch (device globals; no allocation allowed) ----------------
__device__ float g_x[NN*64];
__device__ float g_xl1[NN*64];
__device__ float g_h[NN*64];       // attend output (GRU input)
__device__ float g_p[NN*64];       // raw projection for GATEConv
__device__ float g_mixed[NN*64];
__device__ float g_acc[NN*64];     // edge-weighted accumulator
__device__ float g_denom[NN];
__device__ float g_ai[NN];
__device__ float g_an[NN];
__device__ float g_gout[GG*64];
__device__ float g_accG[GG*64];
__device__ float g_denG[GG];
__device__ float g_gdot[GG];
__device__ float g_hg[GG*64];

__device__ __forceinline__ float leaky(float v){ return v > 0.f ? v : SLOPEF * v; }

__device__ __forceinline__ void red4(float* p, float a, float b, float c, float d){
    asm volatile("red.global.add.v4.f32 [%0], {%1,%2,%3,%4};"
                 :: "l"(p), "f"(a), "f"(b), "f"(c), "f"(d) : "memory");
}

// ---------------- node GEMM: out[n,k] = act(in[n,:]·W[k,:] + b[k]) ----------------
__global__ void k_gemm(float* __restrict__ out, const float* __restrict__ in,
                       const float* __restrict__ W, int ldW,
                       const float* __restrict__ bias, int nrows, int act)
{
    __shared__ float Wt[64*65];
    __shared__ float ins[32*64];
    int tx = threadIdx.x;
    for (int i = tx; i < 4096; i += 256){ int k = i >> 6, d = i & 63; Wt[d*65+k] = W[k*ldW + d]; }
    int base = blockIdx.x * 32;
    int nr = min(32, nrows - base);
    for (int i = tx; i < nr*64; i += 256) ins[i] = in[base*64 + i];
    __syncthreads();
    int k = tx & 63, slot = tx >> 6;
    float acc[8];
    #pragma unroll
    for (int j = 0; j < 8; j++) acc[j] = 0.f;
    for (int d = 0; d < 64; d++){
        float w = Wt[d*65 + k];
        #pragma unroll
        for (int j = 0; j < 8; j++) acc[j] += ins[(slot + 4*j)*64 + d] * w;
    }
    float b = bias ? bias[k] : 0.f;
    #pragma unroll
    for (int j = 0; j < 8; j++){
        int r = base + slot + 4*j;
        if (r < nrows){
            float v = acc[j] + b;
            if (act == 1) v = leaky(v);
            out[r*64 + k] = v;
        }
    }
}

// ---------------- attend GEMM with softmax normalization + elu ----------------
// out[r,k] = elu( (acc[r,:]·W[k,:]) * inv_r + b_k * sumaw_r ),
// inv = 1/(denom+1e-16), sumaw = denom*inv
__global__ void k_attend(float* __restrict__ out, const float* __restrict__ accb,
                         const float* __restrict__ den,
                         const float* __restrict__ W, const float* __restrict__ bias,
                         int nrows)
{
    __shared__ float Wt[64*65];
    __shared__ float ins[32*64];
    __shared__ float dn[32];
    int tx = threadIdx.x;
    for (int i = tx; i < 4096; i += 256){ int k = i >> 6, d = i & 63; Wt[d*65+k] = W[k*64 + d]; }
    int base = blockIdx.x * 32;
    int nr = min(32, nrows - base);
    for (int i = tx; i < nr*64; i += 256) ins[i] = accb[base*64 + i];
    if (tx < nr) dn[tx] = den[base + tx];
    __syncthreads();
    int k = tx & 63, slot = tx >> 6;
    float a[8];
    #pragma unroll
    for (int j = 0; j < 8; j++) a[j] = 0.f;
    for (int d = 0; d < 64; d++){
        float w = Wt[d*65 + k];
        #pragma unroll
        for (int j = 0; j < 8; j++) a[j] += ins[(slot + 4*j)*64 + d] * w;
    }
    float b = bias[k];
    #pragma unroll
    for (int j = 0; j < 8; j++){
        int r = base + slot + 4*j;
        if (r < nrows){
            float dv = dn[slot + 4*j];
            float inv = 1.f / (dv + 1e-16f);
            float v = a[j]*inv + b*(dv*inv);
            out[r*64 + k] = v > 0.f ? v : expm1f(v);
        }
    }
}

// ---------------- per-row dot(s) with 64-vector(s) ----------------
__global__ void k_dot2(float* __restrict__ o1, const float* __restrict__ w1,
                       float* __restrict__ o2, const float* __restrict__ w2,
                       const float* __restrict__ in, int nrows)
{
    int wid  = (blockIdx.x*blockDim.x + threadIdx.x) >> 5;
    int lane = threadIdx.x & 31;
    int nw   = (gridDim.x*blockDim.x) >> 5;
    for (int r = wid; r < nrows; r += nw){
        float v1 = in[r*64 + lane], v2 = in[r*64 + lane + 32];
        float s1 = v1*__ldg(w1+lane) + v2*__ldg(w1+lane+32);
        float s2 = 0.f;
        if (o2) s2 = v1*__ldg(w2+lane) + v2*__ldg(w2+lane+32);
        #pragma unroll
        for (int o = 16; o > 0; o >>= 1){
            s1 += __shfl_xor_sync(0xffffffffu, s1, o);
            s2 += __shfl_xor_sync(0xffffffffu, s2, o);
        }
        if (lane == 0){ o1[r] = s1; if (o2) o2[r] = s2; }
    }
}

// ---------------- GATEConv fused edge pass ----------------
// xj = leaky(p[src] + eattr@We.T), sc = leaky(si[dst] + xj·aj + ab),
// e = exp(sc); denom[dst]+=e; acc[dst]+= e*xj
__global__ void k_gate_edge(const int* __restrict__ ei, const float* __restrict__ eattr,
                            const float* __restrict__ p, const float* __restrict__ si,
                            const float* __restrict__ gate_nl_w,
                            const float* __restrict__ align_w,
                            const float* __restrict__ align_b,
                            float* __restrict__ accb, float* __restrict__ denom)
{
    __shared__ float buf[8][64];
    int tx = threadIdx.x, lane = tx & 31, wl = tx >> 5;
    // per-lane register weights: We^T[d][lane] and We^T[d][lane+32], d=0..15
    float w1r[16], w2r[16];
    #pragma unroll
    for (int i = 0; i < 4; i++){
        float4 v1 = *(const float4*)(gate_nl_w + lane*80 + 64 + 4*i);
        float4 v2 = *(const float4*)(gate_nl_w + (lane+32)*80 + 64 + 4*i);
        w1r[4*i] = v1.x; w1r[4*i+1] = v1.y; w1r[4*i+2] = v1.z; w1r[4*i+3] = v1.w;
        w2r[4*i] = v2.x; w2r[4*i+1] = v2.y; w2r[4*i+2] = v2.z; w2r[4*i+3] = v2.w;
    }
    float aj1 = __ldg(align_w + 64 + lane), aj2 = __ldg(align_w + 96 + lane);
    float ab = __ldg(align_b);
    int wid = (blockIdx.x*blockDim.x + tx) >> 5;
    int nw  = (gridDim.x*blockDim.x) >> 5;
    for (int e = wid; e < EE; e += nw){
        int s = ei[e], t = ei[EE + e];
        float ea = (lane < 16) ? eattr[e*16 + lane] : 0.f;
        float x1 = p[s*64 + lane];
        float x2 = p[s*64 + lane + 32];
        #pragma unroll
        for (int d = 0; d < 16; d++){
            float ed = __shfl_sync(0xffffffffu, ea, d);
            x1 += ed * w1r[d];
            x2 += ed * w2r[d];
        }
        x1 = leaky(x1); x2 = leaky(x2);
        float part = x1*aj1 + x2*aj2;
        #pragma unroll
        for (int o = 16; o > 0; o >>= 1) part += __shfl_xor_sync(0xffffffffu, part, o);
        float ec = 0.f;
        if (lane == 0){
            float sc = leaky(si[t] + part + ab);
            ec = expf(sc);
            atomicAdd(denom + t, ec);
        }
        ec = __shfl_sync(0xffffffffu, ec, 0);
        buf[wl][lane] = x1; buf[wl][lane + 32] = x2;
        __syncwarp();
        if (lane < 16){
            float4 v = *(float4*)&buf[wl][lane*4];
            red4(accb + t*64 + lane*4, ec*v.x, ec*v.y, ec*v.z, ec*v.w);
        }
        __syncwarp();
    }
}

// ---------------- GATConv fused edge pass (2 edges per warp) ----------------
__global__ void k_conv_edge(const int* __restrict__ ei, const float* __restrict__ x,
                            const float* __restrict__ ai, const float* __restrict__ an,
                            const float* __restrict__ bptr,
                            float* __restrict__ accb, float* __restrict__ denom)
{
    float b = __ldg(bptr);
    int tx = threadIdx.x, lane = tx & 31;
    int sub = lane >> 4, l4 = lane & 15;
    int wid = (blockIdx.x*blockDim.x + tx) >> 5;
    int nw  = (gridDim.x*blockDim.x) >> 5;
    for (int pair = wid; pair < EE/2; pair += nw){
        int e = pair*2 + sub;
        int s = ei[e], t = ei[EE + e];
        float ec = expf(leaky(ai[t] + an[s] + b));
        float4 v = *(const float4*)(x + s*64 + l4*4);
        red4(accb + t*64 + l4*4, ec*v.x, ec*v.y, ec*v.z, ec*v.w);
        if (l4 == 0) atomicAdd(denom + t, ec);
    }
}

// ---------------- molecule fused node->graph pass (2 nodes per warp) ----------------
__global__ void k_mol_edge(const int* __restrict__ batch, const float* __restrict__ mixed,
                           const float* __restrict__ gdot, const float* __restrict__ ndot,
                           const float* __restrict__ bptr,
                           float* __restrict__ accG, float* __restrict__ denG)
{
    float b = __ldg(bptr);
    int tx = threadIdx.x, lane = tx & 31;
    int sub = lane >> 4, l4 = lane & 15;
    int wid = (blockIdx.x*blockDim.x + tx) >> 5;
    int nw  = (gridDim.x*blockDim.x) >> 5;
    for (int pair = wid; pair < NN/2; pair += nw){
        int n = pair*2 + sub;
        int g = batch[n];
        float ec = expf(leaky(gdot[g] + ndot[n] + b));
        float4 v = *(const float4*)(mixed + n*64 + l4*4);
        red4(accG + g*64 + l4*4, ec*v.x, ec*v.y, ec*v.z, ec*v.w);
        if (l4 == 0) atomicAdd(denG + g, ec);
    }
}

// ---------------- graph segment sum (2 nodes per warp) ----------------
__global__ void k_segsum(const float* __restrict__ x, const int* __restrict__ batch,
                         float* __restrict__ gout)
{
    int tx = threadIdx.x, lane = tx & 31;
    int sub = lane >> 4, l4 = lane & 15;
    int wid = (blockIdx.x*blockDim.x + tx) >> 5;
    int nw  = (gridDim.x*blockDim.x) >> 5;
    for (int pair = wid; pair < NN/2; pair += nw){
        int n = pair*2 + sub;
        int g = batch[n];
        float4 v = *(const float4*)(x + n*64 + l4*4);
        red4(gout + g*64 + l4*4, v.x, v.y, v.z, v.w);
    }
}

// ---------------- persistent GRU: xout = relu(gru(hin, xprev)) ----------------
__global__ __launch_bounds__(256, 1)
void k_gru(float* __restrict__ xout, const float* __restrict__ hin,
           const float* __restrict__ xprev,
           const float* __restrict__ wih, const float* __restrict__ whh,
           const float* __restrict__ bih, const float* __restrict__ bhh,
           int nrows)
{
    extern __shared__ float sm[];
    float* wt = sm;              // [192][68]
    float* ut = sm + 192*68;     // [192][68]
    float* hs = ut + 192*68;     // [32][68]
    float* xs = hs + 32*68;      // [32][68]
    int tx = threadIdx.x;
    for (int i = tx; i < 3072; i += 256){
        int r = i >> 4, c = (i & 15) * 4;
        *(float4*)&wt[r*68 + c] = *(const float4*)&wih[r*64 + c];
        *(float4*)&ut[r*68 + c] = *(const float4*)&whh[r*64 + c];
    }
    __syncthreads();
    int k = tx & 63, slot = tx >> 6;
    float br = bih[k], bz = bih[64+k], bn = bih[128+k];
    float cr = bhh[k], cz = bhh[64+k], cn = bhh[128+k];
    int ntiles = (nrows + 31) / 32;
    for (int tile = blockIdx.x; tile < ntiles; tile += gridDim.x){
        int base = tile*32, nr = min(32, nrows - base);
        for (int i = tx; i < 2048; i += 256){
            int r = i >> 6, d = i & 63;
            float hv = 0.f, xv = 0.f;
            if (r < nr){ hv = hin[(base+r)*64 + d]; xv = xprev[(base+r)*64 + d]; }
            hs[r*68 + d] = hv; xs[r*68 + d] = xv;
        }
        __syncthreads();
        float a0[8], a1[8], a2[8], a3[8], a4[8], a5[8];
        #pragma unroll
        for (int j = 0; j < 8; j++){ a0[j]=0.f;a1[j]=0.f;a2[j]=0.f;a3[j]=0.f;a4[j]=0.f;a5[j]=0.f; }
        for (int d4 = 0; d4 < 16; d4++){
            float4 w0 = *(float4*)&wt[k*68 + d4*4];
            float4 w1 = *(float4*)&wt[(64+k)*68 + d4*4];
            float4 w2 = *(float4*)&wt[(128+k)*68 + d4*4];
            float4 u0 = *(float4*)&ut[k*68 + d4*4];
            float4 u1 = *(float4*)&ut[(64+k)*68 + d4*4];
            float4 u2 = *(float4*)&ut[(128+k)*68 + d4*4];
            #pragma unroll
            for (int j = 0; j < 8; j++){
                float4 hv = *(float4*)&hs[(slot+4*j)*68 + d4*4];
                float4 xv = *(float4*)&xs[(slot+4*j)*68 + d4*4];
                a0[j] += hv.x*w0.x + hv.y*w0.y + hv.z*w0.z + hv.w*w0.w;
                a1[j] += hv.x*w1.x + hv.y*w1.y + hv.z*w1.z + hv.w*w1.w;
                a2[j] += hv.x*w2.x + hv.y*w2.y + hv.z*w2.z + hv.w*w2.w;
                a3[j] += xv.x*u0.x + xv.y*u0.y + xv.z*u0.z + xv.w*u0.w;
                a4[j] += xv.x*u1.x + xv.y*u1.y + xv.z*u1.z + xv.w*u1.w;
                a5[j] += xv.x*u2.x + xv.y*u2.y + xv.z*u2.z + xv.w*u2.w;
            }
        }
        #pragma unroll
        for (int j = 0; j < 8; j++){
            int r0 = slot + 4*j;
            int row = base + r0;
            if (row < nrows){
                float rr = 1.f/(1.f + expf(-(a0[j]+br + a3[j]+cr)));
                float zz = 1.f/(1.f + expf(-(a1[j]+bz + a4[j]+cz)));
                float nn2 = tanhf(a2[j]+bn + rr*(a5[j]+cn));
                float xp = xs[r0*68 + k];
                float v = (1.f - zz)*nn2 + zz*xp;
                xout[row*64 + k] = fmaxf(v, 0.f);
            }
        }
        __syncthreads();
    }
}

// ---------------- misc ----------------
__global__ void k_relu(float* __restrict__ v, int n)
{
    int i = blockIdx.x*blockDim.x + threadIdx.x;
    int st = gridDim.x*blockDim.x;
    for (; i < n; i += st) v[i] = fmaxf(v[i], 0.f);
}

__global__ void k_mix(float* __restrict__ o, const float* __restrict__ a,
                      const float* __restrict__ b, int n)
{
    int i = blockIdx.x*blockDim.x + threadIdx.x;
    int st = gridDim.x*blockDim.x;
    for (; i < n; i += st) o[i] = 0.5f * (a[i] + b[i]);
}

__global__ void k_final(const float* __restrict__ gout, const float* __restrict__ w,
                        const float* __restrict__ b, float* __restrict__ out, int n)
{
    int wid  = (blockIdx.x*blockDim.x + threadIdx.x) >> 5;
    int lane = threadIdx.x & 31;
    if (wid >= n) return;
    float s = gout[wid*64 + lane]*__ldg(w + lane) + gout[wid*64 + lane + 32]*__ldg(w + lane + 32);
    #pragma unroll
    for (int o = 16; o > 0; o >>= 1) s += __shfl_xor_sync(0xffffffffu, s, o);
    if (lane == 0) out[wid] = s + __ldg(b);
}

// =====================================================================
extern "C" void kernel_launch(void* const* d_in, const int* in_sizes, int n_in,
                              void* d_out_, int out_size)
{
    const float* raw           = (const float*)d_in[0];
    const int*   ei            = (const int*)  d_in[1];
    const float* eattr         = (const float*)d_in[2];
    const int*   batch         = (const int*)  d_in[3];
    const float* lin1_w        = (const float*)d_in[4];
    const float* lin1_b        = (const float*)d_in[5];
    const float* gate_nl_w     = (const float*)d_in[6];
    const float* gate_nl_b     = (const float*)d_in[7];
    const float* gate_align_w  = (const float*)d_in[8];
    const float* gate_align_b  = (const float*)d_in[9];
    const float* gate_attend_w = (const float*)d_in[10];
    const float* gate_attend_b = (const float*)d_in[11];
    const float* conv_align_w  = (const float*)d_in[12];
    const float* conv_align_b  = (const float*)d_in[13];
    const float* conv_attend_w = (const float*)d_in[14];
    const float* conv_attend_b = (const float*)d_in[15];
    const float* agru_wih      = (const float*)d_in[16];
    const float* agru_whh      = (const float*)d_in[17];
    const float* agru_bih      = (const float*)d_in[18];
    const float* agru_bhh      = (const float*)d_in[19];
    const float* mol_align_w   = (const float*)d_in[20];
    const float* mol_align_b   = (const float*)d_in[21];
    const float* mol_attend_w  = (const float*)d_in[22];
    const float* mol_attend_b  = (const float*)d_in[23];
    const float* mgru_wih      = (const float*)d_in[24];
    const float* mgru_whh      = (const float*)d_in[25];
    const float* mgru_bih      = (const float*)d_in[26];
    const float* mgru_bhh      = (const float*)d_in[27];
    const float* lin2_w        = (const float*)d_in[28];
    const float* lin2_b        = (const float*)d_in[29];
    float* outp = (float*)d_out_;

    float *px, *pxl1, *ph, *pp, *pmixed, *pacc, *pdenom, *pai, *pan;
    float *pgout, *paccG, *pdenG, *pgdot, *phg;
    cudaGetSymbolAddress((void**)&px,     g_x);
    cudaGetSymbolAddress((void**)&pxl1,   g_xl1);
    cudaGetSymbolAddress((void**)&ph,     g_h);
    cudaGetSymbolAddress((void**)&pp,     g_p);
    cudaGetSymbolAddress((void**)&pmixed, g_mixed);
    cudaGetSymbolAddress((void**)&pacc,   g_acc);
    cudaGetSymbolAddress((void**)&pdenom, g_denom);
    cudaGetSymbolAddress((void**)&pai,    g_ai);
    cudaGetSymbolAddress((void**)&pan,    g_an);
    cudaGetSymbolAddress((void**)&pgout,  g_gout);
    cudaGetSymbolAddress((void**)&paccG,  g_accG);
    cudaGetSymbolAddress((void**)&pdenG,  g_denG);
    cudaGetSymbolAddress((void**)&pgdot,  g_gdot);
    cudaGetSymbolAddress((void**)&phg,    g_hg);

    const int GRU_SMEM = (2*192*68 + 2*32*68) * 4;   // 121856 bytes
    cudaFuncSetAttribute(k_gru, cudaFuncAttributeMaxDynamicSharedMemorySize, GRU_SMEM);

    const int GBN = (NN + 31) / 32;
    const int GBG = (GG + 31) / 32;

    // ---- input projection + GATEConv precompute ----
    k_gemm<<<GBN, 256>>>(px, raw, lin1_w, 64, lin1_b, NN, 1);           // x = leaky(raw@lin1.T+b)
    k_gemm<<<GBN, 256>>>(pp, raw, gate_nl_w, 80, gate_nl_b, NN, 0);     // p = raw@W_raw.T + b_nl
    k_dot2<<<512, 256>>>(pai, gate_align_w, nullptr, nullptr, px, NN);  // si = x·a_i

    // ---- GATEConv (single fused edge pass) ----
    cudaMemsetAsync(pdenom, 0, NN * sizeof(float));
    cudaMemsetAsync(pacc,   0, NN * 64 * sizeof(float));
    k_gate_edge<<<2048, 256>>>(ei, eattr, pp, pai, gate_nl_w, gate_align_w, gate_align_b,
                               pacc, pdenom);
    k_attend<<<GBN, 256>>>(ph, pacc, pdenom, gate_attend_w, gate_attend_b, NN);
    k_gru<<<148, 256, GRU_SMEM>>>(px, ph, px, agru_wih, agru_whh, agru_bih, agru_bhh, NN);

    // ---- 2x GATConv ----
    for (int l = 0; l < 2; l++){
        k_dot2<<<512, 256>>>(pai, conv_align_w + l*128, pan, conv_align_w + l*128 + 64, px, NN);
        cudaMemsetAsync(pdenom, 0, NN * sizeof(float));
        cudaMemsetAsync(pacc,   0, NN * 64 * sizeof(float));
        k_conv_edge<<<2048, 256>>>(ei, px, pai, pan, conv_align_b + l, pacc, pdenom);
        k_attend<<<GBN, 256>>>(ph, pacc, pdenom, conv_attend_w + l*64*64, conv_attend_b + l*64, NN);
        k_gru<<<148, 256, GRU_SMEM>>>(px, ph, px,
                                      agru_wih + (l+1)*192*64, agru_whh + (l+1)*192*64,
                                      agru_bih + (l+1)*192,    agru_bhh + (l+1)*192, NN);
        if (l == 0)
            cudaMemcpyAsync(pxl1, px, NN * 64 * sizeof(float), cudaMemcpyDeviceToDevice);
    }

    // ---- molecule readout ----
    cudaMemsetAsync(pgout, 0, GG * 64 * sizeof(float));
    k_segsum<<<512, 256>>>(px, batch, pgout);
    k_relu<<<256, 256>>>(pgout, GG * 64);

    for (int t = 0; t < 2; t++){
        const float* mixptr;
        if (t == 0){ k_mix<<<1024, 256>>>(pmixed, px, pxl1, NN * 64); mixptr = pmixed; }
        else       { mixptr = px; }   // cached[-1] == x  => 0.5*(x+x) == x
        k_dot2<<<512, 256>>>(pan,  mol_align_w + 64, nullptr, nullptr, mixptr, NN);  // ndot
        k_dot2<<<64,  256>>>(pgdot, mol_align_w,     nullptr, nullptr, pgout, GG);   // gdot
        cudaMemsetAsync(pdenG, 0, GG * sizeof(float));
        cudaMemsetAsync(paccG, 0, GG * 64 * sizeof(float));
        k_mol_edge<<<512, 256>>>(batch, mixptr, pgdot, pan, mol_align_b, paccG, pdenG);
        k_attend<<<GBG, 256>>>(phg, paccG, pdenG, mol_attend_w, mol_attend_b, GG);
        k_gru<<<148, 256, GRU_SMEM>>>(pgout, phg, pgout, mgru_wih, mgru_whh, mgru_bih, mgru_bhh, GG);
    }

    k_final<<<(GG*32 + 255)/256, 256>>>(pgout, lin2_w, lin2_b, outp, GG);
}

// round 3
// speedup vs baseline: 2.1897x; 1.3900x over previous
#include <cuda_runtime.h>
#include <cuda_bf16.h>
#include <math.h>

#define NN 100000
#define EE 1000000
#define GG 5000
#define SLOPEF 0.01f

// ---------------- scratch (device globals; no allocation allowed) ----------------
__device__ float g_x[NN*64];
__device__ float g_xl1[NN*64];
__device__ float g_h[NN*64];
__device__ float g_p[NN*64];
__device__ float g_mixed[NN*64];
__device__ float g_acc[NN*64];
__device__ float g_denom[NN];
__device__ float g_ai[NN];
__device__ float g_an[NN];
__device__ float g_gout[GG*64];
__device__ float g_accG[GG*64];
__device__ float g_denG[GG];
__device__ float g_gdot[GG];
__device__ float g_hg[GG*64];

__device__ __forceinline__ float leaky(float v){ return v > 0.f ? v : SLOPEF * v; }

__device__ __forceinline__ void red4(float* p, float a, float b, float c, float d){
    asm volatile("red.global.add.v4.f32 [%0], {%1,%2,%3,%4};"
                 :: "l"(p), "f"(a), "f"(b), "f"(c), "f"(d) : "memory");
}
__device__ __forceinline__ void red2(float* p, float a, float b){
    asm volatile("red.global.add.v2.f32 [%0], {%1,%2};"
                 :: "l"(p), "f"(a), "f"(b) : "memory");
}
__device__ __forceinline__ unsigned packbf(float x, float y){
    __nv_bfloat162 t = __floats2bfloat162_rn(x, y);
    return *reinterpret_cast<unsigned*>(&t);
}
__device__ __forceinline__ float bfhi(float x){
    return __bfloat162float(__float2bfloat16_rn(x));
}
__device__ __forceinline__ void mma_bf16(float* c, const unsigned* a, unsigned b0, unsigned b1){
    asm volatile("mma.sync.aligned.m16n8k16.row.col.f32.bf16.bf16.f32 "
                 "{%0,%1,%2,%3},{%4,%5,%6,%7},{%8,%9},{%0,%1,%2,%3};"
                 : "+f"(c[0]), "+f"(c[1]), "+f"(c[2]), "+f"(c[3])
                 : "r"(a[0]), "r"(a[1]), "r"(a[2]), "r"(a[3]), "r"(b0), "r"(b1));
}

// ---------------- node GEMM: out[n,k] = act(in[n,:]·W[k,:] + b[k]) ----------------
__global__ void k_gemm(float* __restrict__ out, const float* __restrict__ in,
                       const float* __restrict__ W, int ldW,
                       const float* __restrict__ bias, int nrows, int act)
{
    __shared__ float Wt[64*65];
    __shared__ float ins[32*64];
    int tx = threadIdx.x;
    for (int i = tx; i < 4096; i += 256){ int k = i >> 6, d = i & 63; Wt[d*65+k] = W[k*ldW + d]; }
    int base = blockIdx.x * 32;
    int nr = min(32, nrows - base);
    for (int i = tx; i < nr*64; i += 256) ins[i] = in[base*64 + i];
    __syncthreads();
    int k = tx & 63, slot = tx >> 6;
    float acc[8];
    #pragma unroll
    for (int j = 0; j < 8; j++) acc[j] = 0.f;
    for (int d = 0; d < 64; d++){
        float w = Wt[d*65 + k];
        #pragma unroll
        for (int j = 0; j < 8; j++) acc[j] += ins[(slot + 4*j)*64 + d] * w;
    }
    float b = bias ? bias[k] : 0.f;
    #pragma unroll
    for (int j = 0; j < 8; j++){
        int r = base + slot + 4*j;
        if (r < nrows){
            float v = acc[j] + b;
            if (act == 1) v = leaky(v);
            out[r*64 + k] = v;
        }
    }
}

// ---------------- attend GEMM with softmax normalization + elu ----------------
__global__ void k_attend(float* __restrict__ out, const float* __restrict__ accb,
                         const float* __restrict__ den,
                         const float* __restrict__ W, const float* __restrict__ bias,
                         int nrows)
{
    __shared__ float Wt[64*65];
    __shared__ float ins[32*64];
    __shared__ float dn[32];
    int tx = threadIdx.x;
    for (int i = tx; i < 4096; i += 256){ int k = i >> 6, d = i & 63; Wt[d*65+k] = W[k*64 + d]; }
    int base = blockIdx.x * 32;
    int nr = min(32, nrows - base);
    for (int i = tx; i < nr*64; i += 256) ins[i] = accb[base*64 + i];
    if (tx < nr) dn[tx] = den[base + tx];
    __syncthreads();
    int k = tx & 63, slot = tx >> 6;
    float a[8];
    #pragma unroll
    for (int j = 0; j < 8; j++) a[j] = 0.f;
    for (int d = 0; d < 64; d++){
        float w = Wt[d*65 + k];
        #pragma unroll
        for (int j = 0; j < 8; j++) a[j] += ins[(slot + 4*j)*64 + d] * w;
    }
    float b = bias[k];
    #pragma unroll
    for (int j = 0; j < 8; j++){
        int r = base + slot + 4*j;
        if (r < nrows){
            float dv = dn[slot + 4*j];
            float inv = 1.f / (dv + 1e-16f);
            float v = a[j]*inv + b*(dv*inv);
            out[r*64 + k] = v > 0.f ? v : expm1f(v);
        }
    }
}

// ---------------- per-row dot(s) with 64-vector(s) ----------------
__global__ void k_dot2(float* __restrict__ o1, const float* __restrict__ w1,
                       float* __restrict__ o2, const float* __restrict__ w2,
                       const float* __restrict__ in, int nrows)
{
    int wid  = (blockIdx.x*blockDim.x + threadIdx.x) >> 5;
    int lane = threadIdx.x & 31;
    int nw   = (gridDim.x*blockDim.x) >> 5;
    for (int r = wid; r < nrows; r += nw){
        float v1 = in[r*64 + lane], v2 = in[r*64 + lane + 32];
        float s1 = v1*__ldg(w1+lane) + v2*__ldg(w1+lane+32);
        float s2 = 0.f;
        if (o2) s2 = v1*__ldg(w2+lane) + v2*__ldg(w2+lane+32);
        #pragma unroll
        for (int o = 16; o > 0; o >>= 1){
            s1 += __shfl_xor_sync(0xffffffffu, s1, o);
            s2 += __shfl_xor_sync(0xffffffffu, s2, o);
        }
        if (lane == 0){ o1[r] = s1; if (o2) o2[r] = s2; }
    }
}

// ---------------- GATEConv fused edge pass (float2 regs, 2 edges/warp-iter) ------
__global__ void k_gate_edge(const int* __restrict__ ei, const float* __restrict__ eattr,
                            const float* __restrict__ p, const float* __restrict__ si,
                            const float* __restrict__ gate_nl_w,
                            const float* __restrict__ align_w,
                            const float* __restrict__ align_b,
                            float* __restrict__ accb, float* __restrict__ denom)
{
    int tx = threadIdx.x, lane = tx & 31;
    float wA[16], wB[16];
    #pragma unroll
    for (int i = 0; i < 4; i++){
        float4 vA = *(const float4*)(gate_nl_w + (2*lane)*80 + 64 + 4*i);
        float4 vB = *(const float4*)(gate_nl_w + (2*lane+1)*80 + 64 + 4*i);
        wA[4*i]=vA.x; wA[4*i+1]=vA.y; wA[4*i+2]=vA.z; wA[4*i+3]=vA.w;
        wB[4*i]=vB.x; wB[4*i+1]=vB.y; wB[4*i+2]=vB.z; wB[4*i+3]=vB.w;
    }
    float2 ajv = *(const float2*)(align_w + 64 + 2*lane);
    float ab = __ldg(align_b);
    int wid = (blockIdx.x*blockDim.x + tx) >> 5;
    int nw  = (gridDim.x*blockDim.x) >> 5;
    for (int e0 = wid*2; e0 < EE; e0 += nw*2){
        int e1 = e0 + 1;
        int s0 = ei[e0], t0 = ei[EE+e0];
        int s1 = ei[e1], t1 = ei[EE+e1];
        float ea0 = (lane < 16) ? eattr[e0*16 + lane] : 0.f;
        float ea1 = (lane < 16) ? eattr[e1*16 + lane] : 0.f;
        float2 pv0 = *(const float2*)(p + s0*64 + 2*lane);
        float2 pv1 = *(const float2*)(p + s1*64 + 2*lane);
        float si0 = __ldg(si + t0), si1 = __ldg(si + t1);
        float x00 = pv0.x, x01 = pv0.y, x10 = pv1.x, x11 = pv1.y;
        #pragma unroll
        for (int d = 0; d < 16; d++){
            float e0d = __shfl_sync(0xffffffffu, ea0, d);
            float e1d = __shfl_sync(0xffffffffu, ea1, d);
            x00 += e0d*wA[d]; x01 += e0d*wB[d];
            x10 += e1d*wA[d]; x11 += e1d*wB[d];
        }
        x00 = leaky(x00); x01 = leaky(x01); x10 = leaky(x10); x11 = leaky(x11);
        float p0 = x00*ajv.x + x01*ajv.y;
        float p1 = x10*ajv.x + x11*ajv.y;
        #pragma unroll
        for (int o = 16; o > 0; o >>= 1){
            p0 += __shfl_xor_sync(0xffffffffu, p0, o);
            p1 += __shfl_xor_sync(0xffffffffu, p1, o);
        }
        float ec0 = 0.f, ec1 = 0.f;
        if (lane == 0){
            ec0 = expf(leaky(si0 + p0 + ab));
            ec1 = expf(leaky(si1 + p1 + ab));
            atomicAdd(denom + t0, ec0);
            atomicAdd(denom + t1, ec1);
        }
        ec0 = __shfl_sync(0xffffffffu, ec0, 0);
        ec1 = __shfl_sync(0xffffffffu, ec1, 0);
        red2(accb + t0*64 + 2*lane, ec0*x00, ec0*x01);
        red2(accb + t1*64 + 2*lane, ec1*x10, ec1*x11);
    }
}

// ---------------- GATConv fused edge pass (4 edges/warp-iter) ----------------
__global__ void k_conv_edge(const int* __restrict__ ei, const float* __restrict__ x,
                            const float* __restrict__ ai, const float* __restrict__ an,
                            const float* __restrict__ bptr,
                            float* __restrict__ accb, float* __restrict__ denom)
{
    float b = __ldg(bptr);
    int tx = threadIdx.x, lane = tx & 31;
    int sub = lane >> 4, l4 = lane & 15;
    int wid = (blockIdx.x*blockDim.x + tx) >> 5;
    int nw  = (gridDim.x*blockDim.x) >> 5;
    for (int q = wid*4; q < EE; q += nw*4){
        int e0 = q + sub*2, e1 = e0 + 1;
        int s0 = ei[e0], t0 = ei[EE+e0];
        int s1 = ei[e1], t1 = ei[EE+e1];
        float a0 = __ldg(ai+t0), n0 = __ldg(an+s0);
        float a1 = __ldg(ai+t1), n1 = __ldg(an+s1);
        float4 v0 = *(const float4*)(x + s0*64 + l4*4);
        float4 v1 = *(const float4*)(x + s1*64 + l4*4);
        float ec0 = expf(leaky(a0 + n0 + b));
        float ec1 = expf(leaky(a1 + n1 + b));
        red4(accb + t0*64 + l4*4, ec0*v0.x, ec0*v0.y, ec0*v0.z, ec0*v0.w);
        red4(accb + t1*64 + l4*4, ec1*v1.x, ec1*v1.y, ec1*v1.z, ec1*v1.w);
        if (l4 == 0){
            atomicAdd(denom + t0, ec0);
            atomicAdd(denom + t1, ec1);
        }
    }
}

// ---------------- molecule fused node->graph pass ----------------
__global__ void k_mol_edge(const int* __restrict__ batch, const float* __restrict__ mixed,
                           const float* __restrict__ gdot, const float* __restrict__ ndot,
                           const float* __restrict__ bptr,
                           float* __restrict__ accG, float* __restrict__ denG)
{
    float b = __ldg(bptr);
    int tx = threadIdx.x, lane = tx & 31;
    int sub = lane >> 4, l4 = lane & 15;
    int wid = (blockIdx.x*blockDim.x + tx) >> 5;
    int nw  = (gridDim.x*blockDim.x) >> 5;
    for (int pair = wid; pair < NN/2; pair += nw){
        int n = pair*2 + sub;
        int g = batch[n];
        float ec = expf(leaky(gdot[g] + ndot[n] + b));
        float4 v = *(const float4*)(mixed + n*64 + l4*4);
        red4(accG + g*64 + l4*4, ec*v.x, ec*v.y, ec*v.z, ec*v.w);
        if (l4 == 0) atomicAdd(denG + g, ec);
    }
}

// ---------------- graph segment sum ----------------
__global__ void k_segsum(const float* __restrict__ x, const int* __restrict__ batch,
                         float* __restrict__ gout)
{
    int tx = threadIdx.x, lane = tx & 31;
    int sub = lane >> 4, l4 = lane & 15;
    int wid = (blockIdx.x*blockDim.x + tx) >> 5;
    int nw  = (gridDim.x*blockDim.x) >> 5;
    for (int pair = wid; pair < NN/2; pair += nw){
        int n = pair*2 + sub;
        int g = batch[n];
        float4 v = *(const float4*)(x + n*64 + l4*4);
        red4(gout + g*64 + l4*4, v.x, v.y, v.z, v.w);
    }
}

// ---------------- GRU via bf16-split tensor-core GEMM ----------------
// C1 = h@wih^T, C2 = x@whh^T (each [rows x 192]), split A,B into bf16 hi+lo:
// C ≈ Ah·Bh + Ah·Bl + Al·Bh  (residual ~2^-16). Epilogue: GRU gates + relu.
#define BLD 200
#define AHLD 36
__global__ __launch_bounds__(256, 1)
void k_gru(float* __restrict__ xout, const float* __restrict__ hin,
           const float* __restrict__ xprev,
           const float* __restrict__ wih, const float* __restrict__ whh,
           const float* __restrict__ bih, const float* __restrict__ bhh,
           int nrows)
{
    extern __shared__ unsigned smu[];
    unsigned* B1h = smu;                 // [32][200] bf16x2 (k-pairs x n)
    unsigned* B1l = B1h + 32*BLD;
    unsigned* B2h = B1l + 32*BLD;
    unsigned* B2l = B2h + 32*BLD;
    unsigned* Ahh = B2l + 32*BLD;        // [64][36] bf16x2
    unsigned* Ahl = Ahh + 64*AHLD;
    unsigned* Axh = Ahl + 64*AHLD;
    unsigned* Axl = Axh + 64*AHLD;
    int tx = threadIdx.x;

    // stage weights (split) once
    for (int i = tx; i < 32*192; i += 256){
        int k2 = i & 31, n = i >> 5;
        float w0 = wih[n*64 + 2*k2], w1 = wih[n*64 + 2*k2 + 1];
        float u0 = whh[n*64 + 2*k2], u1 = whh[n*64 + 2*k2 + 1];
        float w0h = bfhi(w0), w1h = bfhi(w1), u0h = bfhi(u0), u1h = bfhi(u1);
        B1h[k2*BLD + n] = packbf(w0, w1);
        B1l[k2*BLD + n] = packbf(w0 - w0h, w1 - w1h);
        B2h[k2*BLD + n] = packbf(u0, u1);
        B2l[k2*BLD + n] = packbf(u0 - u0h, u1 - u1h);
    }
    __syncthreads();

    int wid = tx >> 5, lane = tx & 31;
    int rowgrp = wid >> 1;      // 0..3 -> 16-row group
    int khalf  = wid & 1;       // 0..1 -> 32 k-cols
    int qrow = lane >> 2, qk = lane & 3;
    int r0 = rowgrp*16;
    int ntile = (nrows + 63) / 64;

    for (int tile = blockIdx.x; tile < ntile; tile += gridDim.x){
        int base = tile * 64;
        // stage A (h and x), split hi/lo
        for (int i = tx; i < 64*32; i += 256){
            int r = i >> 5, k2 = i & 31;
            int row = base + r;
            float h0=0.f,h1=0.f,x0=0.f,x1=0.f;
            if (row < nrows){
                float2 hv = *(const float2*)(hin + row*64 + 2*k2);
                float2 xv = *(const float2*)(xprev + row*64 + 2*k2);
                h0 = hv.x; h1 = hv.y; x0 = xv.x; x1 = xv.y;
            }
            float h0h = bfhi(h0), h1h = bfhi(h1), x0h = bfhi(x0), x1h = bfhi(x1);
            Ahh[r*AHLD + k2] = packbf(h0, h1);
            Ahl[r*AHLD + k2] = packbf(h0 - h0h, h1 - h1h);
            Axh[r*AHLD + k2] = packbf(x0, x1);
            Axl[r*AHLD + k2] = packbf(x0 - x0h, x1 - x1h);
        }
        __syncthreads();

        float c1[12][4], c2[12][4];
        #pragma unroll
        for (int t = 0; t < 12; t++)
            #pragma unroll
            for (int j = 0; j < 4; j++){ c1[t][j] = 0.f; c2[t][j] = 0.f; }

        int ra = (r0 + qrow)*AHLD, rb = (r0 + qrow + 8)*AHLD;
        #pragma unroll
        for (int kt = 0; kt < 4; kt++){
            int pb = kt*8;
            unsigned ahh[4], ahl[4], axh[4], axl[4];
            ahh[0]=Ahh[ra+pb+qk]; ahh[1]=Ahh[rb+pb+qk]; ahh[2]=Ahh[ra+pb+qk+4]; ahh[3]=Ahh[rb+pb+qk+4];
            ahl[0]=Ahl[ra+pb+qk]; ahl[1]=Ahl[rb+pb+qk]; ahl[2]=Ahl[ra+pb+qk+4]; ahl[3]=Ahl[rb+pb+qk+4];
            axh[0]=Axh[ra+pb+qk]; axh[1]=Axh[rb+pb+qk]; axh[2]=Axh[ra+pb+qk+4]; axh[3]=Axh[rb+pb+qk+4];
            axl[0]=Axl[ra+pb+qk]; axl[1]=Axl[rb+pb+qk]; axl[2]=Axl[ra+pb+qk+4]; axl[3]=Axl[rb+pb+qk+4];
            #pragma unroll
            for (int t = 0; t < 12; t++){
                int g = t >> 2, i = t & 3;
                int n0 = g*64 + khalf*32 + i*8 + qrow;
                int o0 = (pb+qk)*BLD + n0, o1 = (pb+4+qk)*BLD + n0;
                unsigned b0h = B1h[o0], b1h = B1h[o1];
                mma_bf16(c1[t], ahh, b0h, b1h);
                mma_bf16(c1[t], ahh, B1l[o0], B1l[o1]);
                mma_bf16(c1[t], ahl, b0h, b1h);
                unsigned d0h = B2h[o0], d1h = B2h[o1];
                mma_bf16(c2[t], axh, d0h, d1h);
                mma_bf16(c2[t], axh, B2l[o0], B2l[o1]);
                mma_bf16(c2[t], axl, d0h, d1h);
            }
        }

        // epilogue: GRU gates
        #pragma unroll
        for (int i = 0; i < 4; i++){
            int kc0 = khalf*32 + i*8 + 2*qk;
            #pragma unroll
            for (int half = 0; half < 2; half++){
                int grow = base + r0 + qrow + half*8;
                if (grow < nrows){
                    float2 xp = *(const float2*)(xprev + grow*64 + kc0);
                    #pragma unroll
                    for (int cc = 0; cc < 2; cc++){
                        int kc = kc0 + cc, ci = half*2 + cc;
                        float sr = c1[i][ci]   + c2[i][ci]   + __ldg(bih+kc)      + __ldg(bhh+kc);
                        float sz = c1[4+i][ci] + c2[4+i][ci] + __ldg(bih+64+kc)  + __ldg(bhh+64+kc);
                        float hn = c2[8+i][ci] + __ldg(bhh+128+kc);
                        float rr = 1.f/(1.f + expf(-sr));
                        float zz = 1.f/(1.f + expf(-sz));
                        float nn = tanhf(c1[8+i][ci] + __ldg(bih+128+kc) + rr*hn);
                        float xv = cc ? xp.y : xp.x;
                        xout[grow*64 + kc] = fmaxf((1.f - zz)*nn + zz*xv, 0.f);
                    }
                }
            }
        }
        __syncthreads();
    }
}

// ---------------- misc ----------------
__global__ void k_relu(float* __restrict__ v, int n)
{
    int i = blockIdx.x*blockDim.x + threadIdx.x;
    int st = gridDim.x*blockDim.x;
    for (; i < n; i += st) v[i] = fmaxf(v[i], 0.f);
}

__global__ void k_mix(float* __restrict__ o, const float* __restrict__ a,
                      const float* __restrict__ b, int n)
{
    int i = blockIdx.x*blockDim.x + threadIdx.x;
    int st = gridDim.x*blockDim.x;
    for (; i < n; i += st) o[i] = 0.5f * (a[i] + b[i]);
}

__global__ void k_final(const float* __restrict__ gout, const float* __restrict__ w,
                        const float* __restrict__ b, float* __restrict__ out, int n)
{
    int wid  = (blockIdx.x*blockDim.x + threadIdx.x) >> 5;
    int lane = threadIdx.x & 31;
    if (wid >= n) return;
    float s = gout[wid*64 + lane]*__ldg(w + lane) + gout[wid*64 + lane + 32]*__ldg(w + lane + 32);
    #pragma unroll
    for (int o = 16; o > 0; o >>= 1) s += __shfl_xor_sync(0xffffffffu, s, o);
    if (lane == 0) out[wid] = s + __ldg(b);
}

// =====================================================================
extern "C" void kernel_launch(void* const* d_in, const int* in_sizes, int n_in,
                              void* d_out_, int out_size)
{
    const float* raw           = (const float*)d_in[0];
    const int*   ei            = (const int*)  d_in[1];
    const float* eattr         = (const float*)d_in[2];
    const int*   batch         = (const int*)  d_in[3];
    const float* lin1_w        = (const float*)d_in[4];
    const float* lin1_b        = (const float*)d_in[5];
    const float* gate_nl_w     = (const float*)d_in[6];
    const float* gate_nl_b     = (const float*)d_in[7];
    const float* gate_align_w  = (const float*)d_in[8];
    const float* gate_align_b  = (const float*)d_in[9];
    const float* gate_attend_w = (const float*)d_in[10];
    const float* gate_attend_b = (const float*)d_in[11];
    const float* conv_align_w  = (const float*)d_in[12];
    const float* conv_align_b  = (const float*)d_in[13];
    const float* conv_attend_w = (const float*)d_in[14];
    const float* conv_attend_b = (const float*)d_in[15];
    const float* agru_wih      = (const float*)d_in[16];
    const float* agru_whh      = (const float*)d_in[17];
    const float* agru_bih      = (const float*)d_in[18];
    const float* agru_bhh      = (const float*)d_in[19];
    const float* mol_align_w   = (const float*)d_in[20];
    const float* mol_align_b   = (const float*)d_in[21];
    const float* mol_attend_w  = (const float*)d_in[22];
    const float* mol_attend_b  = (const float*)d_in[23];
    const float* mgru_wih      = (const float*)d_in[24];
    const float* mgru_whh      = (const float*)d_in[25];
    const float* mgru_bih      = (const float*)d_in[26];
    const float* mgru_bhh      = (const float*)d_in[27];
    const float* lin2_w        = (const float*)d_in[28];
    const float* lin2_b        = (const float*)d_in[29];
    float* outp = (float*)d_out_;

    float *px, *pxl1, *ph, *pp, *pmixed, *pacc, *pdenom, *pai, *pan;
    float *pgout, *paccG, *pdenG, *pgdot, *phg;
    cudaGetSymbolAddress((void**)&px,     g_x);
    cudaGetSymbolAddress((void**)&pxl1,   g_xl1);
    cudaGetSymbolAddress((void**)&ph,     g_h);
    cudaGetSymbolAddress((void**)&pp,     g_p);
    cudaGetSymbolAddress((void**)&pmixed, g_mixed);
    cudaGetSymbolAddress((void**)&pacc,   g_acc);
    cudaGetSymbolAddress((void**)&pdenom, g_denom);
    cudaGetSymbolAddress((void**)&pai,    g_ai);
    cudaGetSymbolAddress((void**)&pan,    g_an);
    cudaGetSymbolAddress((void**)&pgout,  g_gout);
    cudaGetSymbolAddress((void**)&paccG,  g_accG);
    cudaGetSymbolAddress((void**)&pdenG,  g_denG);
    cudaGetSymbolAddress((void**)&pgdot,  g_gdot);
    cudaGetSymbolAddress((void**)&phg,    g_hg);

    const int GRU_SMEM = (4*32*BLD + 4*64*AHLD) * 4;   // 139264 bytes
    cudaFuncSetAttribute(k_gru, cudaFuncAttributeMaxDynamicSharedMemorySize, GRU_SMEM);

    const int GBN = (NN + 31) / 32;
    const int GBG = (GG + 31) / 32;

    // ---- input projection + GATEConv precompute ----
    k_gemm<<<GBN, 256>>>(px, raw, lin1_w, 64, lin1_b, NN, 1);
    k_gemm<<<GBN, 256>>>(pp, raw, gate_nl_w, 80, gate_nl_b, NN, 0);
    k_dot2<<<512, 256>>>(pai, gate_align_w, nullptr, nullptr, px, NN);

    // ---- GATEConv ----
    cudaMemsetAsync(pdenom, 0, NN * sizeof(float));
    cudaMemsetAsync(pacc,   0, NN * 64 * sizeof(float));
    k_gate_edge<<<2048, 256>>>(ei, eattr, pp, pai, gate_nl_w, gate_align_w, gate_align_b,
                               pacc, pdenom);
    k_attend<<<GBN, 256>>>(ph, pacc, pdenom, gate_attend_w, gate_attend_b, NN);
    k_gru<<<148, 256, GRU_SMEM>>>(px, ph, px, agru_wih, agru_whh, agru_bih, agru_bhh, NN);

    // ---- 2x GATConv ----
    for (int l = 0; l < 2; l++){
        k_dot2<<<512, 256>>>(pai, conv_align_w + l*128, pan, conv_align_w + l*128 + 64, px, NN);
        cudaMemsetAsync(pdenom, 0, NN * sizeof(float));
        cudaMemsetAsync(pacc,   0, NN * 64 * sizeof(float));
        k_conv_edge<<<2048, 256>>>(ei, px, pai, pan, conv_align_b + l, pacc, pdenom);
        k_attend<<<GBN, 256>>>(ph, pacc, pdenom, conv_attend_w + l*64*64, conv_attend_b + l*64, NN);
        k_gru<<<148, 256, GRU_SMEM>>>(px, ph, px,
                                      agru_wih + (l+1)*192*64, agru_whh + (l+1)*192*64,
                                      agru_bih + (l+1)*192,    agru_bhh + (l+1)*192, NN);
        if (l == 0)
            cudaMemcpyAsync(pxl1, px, NN * 64 * sizeof(float), cudaMemcpyDeviceToDevice);
    }

    // ---- molecule readout ----
    cudaMemsetAsync(pgout, 0, GG * 64 * sizeof(float));
    k_segsum<<<512, 256>>>(px, batch, pgout);
    k_relu<<<256, 256>>>(pgout, GG * 64);

    for (int t = 0; t < 2; t++){
        const float* mixptr;
        if (t == 0){ k_mix<<<1024, 256>>>(pmixed, px, pxl1, NN * 64); mixptr = pmixed; }
        else       { mixptr = px; }
        k_dot2<<<512, 256>>>(pan,  mol_align_w + 64, nullptr, nullptr, mixptr, NN);
        k_dot2<<<64,  256>>>(pgdot, mol_align_w,     nullptr, nullptr, pgout, GG);
        cudaMemsetAsync(pdenG, 0, GG * sizeof(float));
        cudaMemsetAsync(paccG, 0, GG * 64 * sizeof(float));
        k_mol_edge<<<512, 256>>>(batch, mixptr, pgdot, pan, mol_align_b, paccG, pdenG);
        k_attend<<<GBG, 256>>>(phg, paccG, pdenG, mol_attend_w, mol_attend_b, GG);
        k_gru<<<148, 256, GRU_SMEM>>>(pgout, phg, pgout, mgru_wih, mgru_whh, mgru_bih, mgru_bhh, GG);
    }

    k_final<<<(GG*32 + 255)/256, 256>>>(pgout, lin2_w, lin2_b, outp, GG);
}

// round 4
// speedup vs baseline: 2.6319x; 1.2020x over previous
#include <cuda_runtime.h>
#include <cuda_bf16.h>
#include <math.h>

#define NN 100000
#define EE 1000000
#define GG 5000
#define SLOPEF 0.01f

// ---------------- scratch (device globals; no allocation allowed) ----------------
__device__ float g_x[NN*64];
__device__ float g_xl1[NN*64];
__device__ float g_h[NN*64];
__device__ float g_p[NN*64];
__device__ float g_mixed[NN*64];
__device__ float g_dots[2*NN];        // pai | pan
__device__ float g_pan2[NN];
__device__ float g_accd[NN*64 + NN];  // pacc | pdenom
__device__ float g_gout[GG*64];
__device__ float g_molaccd[GG*64 + GG]; // accG | denG
__device__ float g_gdot[GG];
__device__ float g_hg[GG*64];

__device__ __forceinline__ float leaky(float v){ return v > 0.f ? v : SLOPEF * v; }

__device__ __forceinline__ void red4(float* p, float a, float b, float c, float d){
    asm volatile("red.global.add.v4.f32 [%0], {%1,%2,%3,%4};"
                 :: "l"(p), "f"(a), "f"(b), "f"(c), "f"(d) : "memory");
}
__device__ __forceinline__ void red2(float* p, float a, float b){
    asm volatile("red.global.add.v2.f32 [%0], {%1,%2};"
                 :: "l"(p), "f"(a), "f"(b) : "memory");
}
__device__ __forceinline__ unsigned packbf(float x, float y){
    __nv_bfloat162 t = __floats2bfloat162_rn(x, y);
    return *reinterpret_cast<unsigned*>(&t);
}
__device__ __forceinline__ float bfhi(float x){
    return __bfloat162float(__float2bfloat16_rn(x));
}
__device__ __forceinline__ void mma_bf16(float* c, const unsigned* a, unsigned b0, unsigned b1){
    asm volatile("mma.sync.aligned.m16n8k16.row.col.f32.bf16.bf16.f32 "
                 "{%0,%1,%2,%3},{%4,%5,%6,%7},{%8,%9},{%0,%1,%2,%3};"
                 : "+f"(c[0]), "+f"(c[1]), "+f"(c[2]), "+f"(c[3])
                 : "r"(a[0]), "r"(a[1]), "r"(a[2]), "r"(a[3]), "r"(b0), "r"(b1));
}

// ================= unified node GEMM (tensor cores, bf16 split) =================
// out[r,n] = epilogue( in[r,:]·W[n,:] )
// mode 0: +bias
// mode 1: leaky(+bias), optional row-dot with dotw accumulated into dotout (atomic)
// mode 2: attend: elu( c*inv + bias*(den*inv) ), and zero in (=acc) and den in place
#define MB 72
#define MA 36
__global__ __launch_bounds__(256)
void k_mm(float* __restrict__ out, const float* __restrict__ in,
          const float* __restrict__ W, int ldW, const float* __restrict__ bias,
          float* __restrict__ den, float* __restrict__ accz,
          const float* __restrict__ dotw, float* __restrict__ dotout,
          int nrows, int mode)
{
    __shared__ unsigned Bh[32*MB], Bl[32*MB];
    __shared__ unsigned Ah[64*MA], Al[64*MA];
    __shared__ float dens[64];
    int tx = threadIdx.x;
    for (int i = tx; i < 2048; i += 256){
        int k2 = i >> 6, n = i & 63;
        float w0 = W[n*ldW + 2*k2], w1 = W[n*ldW + 2*k2 + 1];
        float w0h = bfhi(w0), w1h = bfhi(w1);
        Bh[k2*MB + n] = packbf(w0, w1);
        Bl[k2*MB + n] = packbf(w0 - w0h, w1 - w1h);
    }
    int wid = tx >> 5, lane = tx & 31;
    int rowgrp = wid >> 1, khalf = wid & 1;
    int qrow = lane >> 2, qk = lane & 3;
    int r0 = rowgrp * 16;
    int ntile = (nrows + 63) >> 6;
    for (int tile = blockIdx.x; tile < ntile; tile += gridDim.x){
        int base = tile << 6;
        __syncthreads();
        for (int i = tx; i < 2048; i += 256){
            int r = i >> 5, k2 = i & 31;
            int row = base + r;
            float2 v = make_float2(0.f, 0.f);
            if (row < nrows){
                v = *(const float2*)(in + row*64 + 2*k2);
                if (mode == 2) *(float2*)(accz + row*64 + 2*k2) = make_float2(0.f, 0.f);
            }
            float vxh = bfhi(v.x), vyh = bfhi(v.y);
            Ah[r*MA + k2] = packbf(v.x, v.y);
            Al[r*MA + k2] = packbf(v.x - vxh, v.y - vyh);
        }
        if (mode == 2 && tx < 64){
            int row = base + tx;
            float dv = 0.f;
            if (row < nrows){ dv = den[row]; den[row] = 0.f; }
            dens[tx] = dv;
        }
        __syncthreads();

        float c[4][4];
        #pragma unroll
        for (int t = 0; t < 4; t++)
            #pragma unroll
            for (int j = 0; j < 4; j++) c[t][j] = 0.f;

        int ra = (r0 + qrow)*MA, rb = (r0 + qrow + 8)*MA;
        #pragma unroll
        for (int kt = 0; kt < 4; kt++){
            int pb = kt*8;
            unsigned ah[4], al[4];
            ah[0]=Ah[ra+pb+qk]; ah[1]=Ah[rb+pb+qk]; ah[2]=Ah[ra+pb+qk+4]; ah[3]=Ah[rb+pb+qk+4];
            al[0]=Al[ra+pb+qk]; al[1]=Al[rb+pb+qk]; al[2]=Al[ra+pb+qk+4]; al[3]=Al[rb+pb+qk+4];
            #pragma unroll
            for (int t = 0; t < 4; t++){
                int n0 = khalf*32 + t*8 + qrow;
                int o0 = (pb+qk)*MB + n0, o1 = (pb+4+qk)*MB + n0;
                unsigned b0 = Bh[o0], b1 = Bh[o1];
                mma_bf16(c[t], ah, b0, b1);
                mma_bf16(c[t], ah, Bl[o0], Bl[o1]);
                mma_bf16(c[t], al, b0, b1);
            }
        }

        float pd[2] = {0.f, 0.f};
        #pragma unroll
        for (int t = 0; t < 4; t++){
            int kc0 = khalf*32 + t*8 + 2*qk;
            float b0 = __ldg(bias + kc0), b1 = __ldg(bias + kc0 + 1);
            #pragma unroll
            for (int half = 0; half < 2; half++){
                int grow = base + r0 + qrow + 8*half;
                if (grow < nrows){
                    float v0 = c[t][2*half], v1 = c[t][2*half+1];
                    if (mode == 2){
                        float dv = dens[r0 + qrow + 8*half];
                        float inv = 1.f / (dv + 1e-16f);
                        float sc = dv * inv;
                        v0 = v0*inv + b0*sc; v1 = v1*inv + b1*sc;
                        v0 = v0 > 0.f ? v0 : expm1f(v0);
                        v1 = v1 > 0.f ? v1 : expm1f(v1);
                    } else {
                        v0 += b0; v1 += b1;
                        if (mode == 1){ v0 = leaky(v0); v1 = leaky(v1); }
                    }
                    *(float2*)(out + grow*64 + kc0) = make_float2(v0, v1);
                    if (dotw) pd[half] += v0*__ldg(dotw+kc0) + v1*__ldg(dotw+kc0+1);
                }
            }
        }
        if (dotw){
            #pragma unroll
            for (int o = 1; o <= 2; o <<= 1){
                pd[0] += __shfl_xor_sync(0xffffffffu, pd[0], o);
                pd[1] += __shfl_xor_sync(0xffffffffu, pd[1], o);
            }
            if (qk == 0){
                #pragma unroll
                for (int half = 0; half < 2; half++){
                    int grow = base + r0 + qrow + 8*half;
                    if (grow < nrows) atomicAdd(dotout + grow, pd[half]);
                }
            }
        }
    }
}

// ---------------- GATEConv fused edge pass (smem weights) ----------------
__global__ void k_gate_edge(const int* __restrict__ ei, const float* __restrict__ eattr,
                            const float* __restrict__ p, const float* __restrict__ si,
                            const float* __restrict__ gate_nl_w,
                            const float* __restrict__ align_w,
                            const float* __restrict__ align_b,
                            float* __restrict__ accb, float* __restrict__ denom)
{
    __shared__ float2 sw[16][32];
    int tx = threadIdx.x, lane = tx & 31;
    for (int i = tx; i < 512; i += 256){
        int d = i >> 5, l = i & 31;
        sw[d][l] = make_float2(gate_nl_w[(2*l)*80 + 64 + d], gate_nl_w[(2*l+1)*80 + 64 + d]);
    }
    __syncthreads();
    float2 ajv = *(const float2*)(align_w + 64 + 2*lane);
    float ab = __ldg(align_b);
    int wid = (blockIdx.x*blockDim.x + tx) >> 5;
    int nw  = (gridDim.x*blockDim.x) >> 5;
    for (int e0 = wid*2; e0 < EE; e0 += nw*2){
        int e1 = e0 + 1;
        int s0 = ei[e0], t0 = ei[EE+e0];
        int s1 = ei[e1], t1 = ei[EE+e1];
        float ea0 = (lane < 16) ? eattr[e0*16 + lane] : 0.f;
        float ea1 = (lane < 16) ? eattr[e1*16 + lane] : 0.f;
        float2 pv0 = *(const float2*)(p + s0*64 + 2*lane);
        float2 pv1 = *(const float2*)(p + s1*64 + 2*lane);
        float si0 = __ldg(si + t0), si1 = __ldg(si + t1);
        float x00 = pv0.x, x01 = pv0.y, x10 = pv1.x, x11 = pv1.y;
        #pragma unroll
        for (int d = 0; d < 16; d++){
            float2 w = sw[d][lane];
            float e0d = __shfl_sync(0xffffffffu, ea0, d);
            float e1d = __shfl_sync(0xffffffffu, ea1, d);
            x00 += e0d*w.x; x01 += e0d*w.y;
            x10 += e1d*w.x; x11 += e1d*w.y;
        }
        x00 = leaky(x00); x01 = leaky(x01); x10 = leaky(x10); x11 = leaky(x11);
        float p0 = x00*ajv.x + x01*ajv.y;
        float p1 = x10*ajv.x + x11*ajv.y;
        #pragma unroll
        for (int o = 16; o > 0; o >>= 1){
            p0 += __shfl_xor_sync(0xffffffffu, p0, o);
            p1 += __shfl_xor_sync(0xffffffffu, p1, o);
        }
        float ec0 = 0.f, ec1 = 0.f;
        if (lane == 0){
            ec0 = expf(leaky(si0 + p0 + ab));
            ec1 = expf(leaky(si1 + p1 + ab));
            atomicAdd(denom + t0, ec0);
            atomicAdd(denom + t1, ec1);
        }
        ec0 = __shfl_sync(0xffffffffu, ec0, 0);
        ec1 = __shfl_sync(0xffffffffu, ec1, 0);
        red2(accb + t0*64 + 2*lane, ec0*x00, ec0*x01);
        red2(accb + t1*64 + 2*lane, ec1*x10, ec1*x11);
    }
}

// ---------------- GATConv fused edge pass (4 edges/warp-iter) ----------------
__global__ void k_conv_edge(const int* __restrict__ ei, const float* __restrict__ x,
                            const float* __restrict__ ai, const float* __restrict__ an,
                            const float* __restrict__ bptr,
                            float* __restrict__ accb, float* __restrict__ denom)
{
    float b = __ldg(bptr);
    int tx = threadIdx.x, lane = tx & 31;
    int sub = lane >> 4, l4 = lane & 15;
    int wid = (blockIdx.x*blockDim.x + tx) >> 5;
    int nw  = (gridDim.x*blockDim.x) >> 5;
    for (int q = wid*4; q < EE; q += nw*4){
        int e0 = q + sub*2, e1 = e0 + 1;
        int s0 = ei[e0], t0 = ei[EE+e0];
        int s1 = ei[e1], t1 = ei[EE+e1];
        float a0 = __ldg(ai+t0), n0 = __ldg(an+s0);
        float a1 = __ldg(ai+t1), n1 = __ldg(an+s1);
        float4 v0 = *(const float4*)(x + s0*64 + l4*4);
        float4 v1 = *(const float4*)(x + s1*64 + l4*4);
        float ec0 = expf(leaky(a0 + n0 + b));
        float ec1 = expf(leaky(a1 + n1 + b));
        red4(accb + t0*64 + l4*4, ec0*v0.x, ec0*v0.y, ec0*v0.z, ec0*v0.w);
        red4(accb + t1*64 + l4*4, ec1*v1.x, ec1*v1.y, ec1*v1.z, ec1*v1.w);
        if (l4 == 0){
            atomicAdd(denom + t0, ec0);
            atomicAdd(denom + t1, ec1);
        }
    }
}

// ---------------- molecule fused node->graph pass ----------------
__global__ void k_mol_edge(const int* __restrict__ batch, const float* __restrict__ mixed,
                           const float* __restrict__ gdot, const float* __restrict__ ndot,
                           const float* __restrict__ bptr,
                           float* __restrict__ accG, float* __restrict__ denG)
{
    float b = __ldg(bptr);
    int tx = threadIdx.x, lane = tx & 31;
    int sub = lane >> 4, l4 = lane & 15;
    int wid = (blockIdx.x*blockDim.x + tx) >> 5;
    int nw  = (gridDim.x*blockDim.x) >> 5;
    for (int pair = wid; pair < NN/2; pair += nw){
        int n = pair*2 + sub;
        int g = batch[n];
        float ec = expf(leaky(gdot[g] + ndot[n] + b));
        float4 v = *(const float4*)(mixed + n*64 + l4*4);
        red4(accG + g*64 + l4*4, ec*v.x, ec*v.y, ec*v.z, ec*v.w);
        if (l4 == 0) atomicAdd(denG + g, ec);
    }
}

// ---------------- GRU via bf16-split tensor-core GEMM ----------------
#define BLD 200
#define AHLD 36
__global__ __launch_bounds__(256, 1)
void k_gru(float* __restrict__ xout, float* __restrict__ xout2,
           const float* __restrict__ hin, const float* __restrict__ xprev,
           const float* __restrict__ wih, const float* __restrict__ whh,
           const float* __restrict__ bih, const float* __restrict__ bhh,
           const float* __restrict__ dotw1, const float* __restrict__ dotw2,
           float* __restrict__ dot1, float* __restrict__ dot2,
           const int* __restrict__ batchv, float* __restrict__ gsum,
           int nrows)
{
    extern __shared__ unsigned smu[];
    unsigned* B1h = smu;
    unsigned* B1l = B1h + 32*BLD;
    unsigned* B2h = B1l + 32*BLD;
    unsigned* B2l = B2h + 32*BLD;
    unsigned* Ahh = B2l + 32*BLD;
    unsigned* Ahl = Ahh + 64*AHLD;
    unsigned* Axh = Ahl + 64*AHLD;
    unsigned* Axl = Axh + 64*AHLD;
    int tx = threadIdx.x;

    for (int i = tx; i < 32*192; i += 256){
        int k2 = i & 31, n = i >> 5;
        float w0 = wih[n*64 + 2*k2], w1 = wih[n*64 + 2*k2 + 1];
        float u0 = whh[n*64 + 2*k2], u1 = whh[n*64 + 2*k2 + 1];
        float w0h = bfhi(w0), w1h = bfhi(w1), u0h = bfhi(u0), u1h = bfhi(u1);
        B1h[k2*BLD + n] = packbf(w0, w1);
        B1l[k2*BLD + n] = packbf(w0 - w0h, w1 - w1h);
        B2h[k2*BLD + n] = packbf(u0, u1);
        B2l[k2*BLD + n] = packbf(u0 - u0h, u1 - u1h);
    }
    __syncthreads();

    int wid = tx >> 5, lane = tx & 31;
    int rowgrp = wid >> 1;
    int khalf  = wid & 1;
    int qrow = lane >> 2, qk = lane & 3;
    int r0 = rowgrp*16;
    int ntile = (nrows + 63) / 64;

    for (int tile = blockIdx.x; tile < ntile; tile += gridDim.x){
        int base = tile * 64;
        for (int i = tx; i < 64*32; i += 256){
            int r = i >> 5, k2 = i & 31;
            int row = base + r;
            float h0=0.f,h1=0.f,x0=0.f,x1=0.f;
            if (row < nrows){
                float2 hv = *(const float2*)(hin + row*64 + 2*k2);
                float2 xv = *(const float2*)(xprev + row*64 + 2*k2);
                h0 = hv.x; h1 = hv.y; x0 = xv.x; x1 = xv.y;
            }
            float h0h = bfhi(h0), h1h = bfhi(h1), x0h = bfhi(x0), x1h = bfhi(x1);
            Ahh[r*AHLD + k2] = packbf(h0, h1);
            Ahl[r*AHLD + k2] = packbf(h0 - h0h, h1 - h1h);
            Axh[r*AHLD + k2] = packbf(x0, x1);
            Axl[r*AHLD + k2] = packbf(x0 - x0h, x1 - x1h);
        }
        __syncthreads();

        float c1[12][4], c2[12][4];
        #pragma unroll
        for (int t = 0; t < 12; t++)
            #pragma unroll
            for (int j = 0; j < 4; j++){ c1[t][j] = 0.f; c2[t][j] = 0.f; }

        int ra = (r0 + qrow)*AHLD, rb = (r0 + qrow + 8)*AHLD;
        #pragma unroll
        for (int kt = 0; kt < 4; kt++){
            int pb = kt*8;
            unsigned ahh[4], ahl[4], axh[4], axl[4];
            ahh[0]=Ahh[ra+pb+qk]; ahh[1]=Ahh[rb+pb+qk]; ahh[2]=Ahh[ra+pb+qk+4]; ahh[3]=Ahh[rb+pb+qk+4];
            ahl[0]=Ahl[ra+pb+qk]; ahl[1]=Ahl[rb+pb+qk]; ahl[2]=Ahl[ra+pb+qk+4]; ahl[3]=Ahl[rb+pb+qk+4];
            axh[0]=Axh[ra+pb+qk]; axh[1]=Axh[rb+pb+qk]; axh[2]=Axh[ra+pb+qk+4]; axh[3]=Axh[rb+pb+qk+4];
            axl[0]=Axl[ra+pb+qk]; axl[1]=Axl[rb+pb+qk]; axl[2]=Axl[ra+pb+qk+4]; axl[3]=Axl[rb+pb+qk+4];
            #pragma unroll
            for (int t = 0; t < 12; t++){
                int g = t >> 2, i = t & 3;
                int n0 = g*64 + khalf*32 + i*8 + qrow;
                int o0 = (pb+qk)*BLD + n0, o1 = (pb+4+qk)*BLD + n0;
                unsigned b0h = B1h[o0], b1h = B1h[o1];
                mma_bf16(c1[t], ahh, b0h, b1h);
                mma_bf16(c1[t], ahh, B1l[o0], B1l[o1]);
                mma_bf16(c1[t], ahl, b0h, b1h);
                unsigned d0h = B2h[o0], d1h = B2h[o1];
                mma_bf16(c2[t], axh, d0h, d1h);
                mma_bf16(c2[t], axh, B2l[o0], B2l[o1]);
                mma_bf16(c2[t], axl, d0h, d1h);
            }
        }

        float pd1[2] = {0.f, 0.f}, pd2[2] = {0.f, 0.f};
        #pragma unroll
        for (int half = 0; half < 2; half++){
            int grow = base + r0 + qrow + 8*half;
            if (grow < nrows){
                int gseg = batchv ? __ldg(batchv + grow) : 0;
                #pragma unroll
                for (int i = 0; i < 4; i++){
                    int kc0 = khalf*32 + i*8 + 2*qk;
                    float2 xp = *(const float2*)(xprev + grow*64 + kc0);
                    float v[2];
                    #pragma unroll
                    for (int cc = 0; cc < 2; cc++){
                        int kc = kc0 + cc, ci = half*2 + cc;
                        float sr = c1[i][ci]   + c2[i][ci]   + __ldg(bih+kc)     + __ldg(bhh+kc);
                        float sz = c1[4+i][ci] + c2[4+i][ci] + __ldg(bih+64+kc) + __ldg(bhh+64+kc);
                        float hn = c2[8+i][ci] + __ldg(bhh+128+kc);
                        float rr = 1.f/(1.f + expf(-sr));
                        float zz = 1.f/(1.f + expf(-sz));
                        float nn = tanhf(c1[8+i][ci] + __ldg(bih+128+kc) + rr*hn);
                        float xv = cc ? xp.y : xp.x;
                        v[cc] = fmaxf((1.f - zz)*nn + zz*xv, 0.f);
                    }
                    float2 o = make_float2(v[0], v[1]);
                    *(float2*)(xout + grow*64 + kc0) = o;
                    if (xout2) *(float2*)(xout2 + grow*64 + kc0) = o;
                    if (dotw1) pd1[half] += v[0]*__ldg(dotw1+kc0) + v[1]*__ldg(dotw1+kc0+1);
                    if (dotw2) pd2[half] += v[0]*__ldg(dotw2+kc0) + v[1]*__ldg(dotw2+kc0+1);
                    if (gsum) red2(gsum + gseg*64 + kc0, v[0], v[1]);
                }
            }
        }
        if (dotw1){
            #pragma unroll
            for (int o = 1; o <= 2; o <<= 1){
                pd1[0] += __shfl_xor_sync(0xffffffffu, pd1[0], o);
                pd1[1] += __shfl_xor_sync(0xffffffffu, pd1[1], o);
                pd2[0] += __shfl_xor_sync(0xffffffffu, pd2[0], o);
                pd2[1] += __shfl_xor_sync(0xffffffffu, pd2[1], o);
            }
            if (qk == 0){
                #pragma unroll
                for (int half = 0; half < 2; half++){
                    int grow = base + r0 + qrow + 8*half;
                    if (grow < nrows){
                        atomicAdd(dot1 + grow, pd1[half]);
                        if (dotw2) atomicAdd(dot2 + grow, pd2[half]);
                    }
                }
            }
        }
        __syncthreads();
    }
}

// ---------------- per-row dot, optional in-place relu ----------------
__global__ void k_dotg(float* __restrict__ o1, const float* __restrict__ w1,
                       float* __restrict__ in, int nrows, int dorelu)
{
    int wid  = (blockIdx.x*blockDim.x + threadIdx.x) >> 5;
    int lane = threadIdx.x & 31;
    int nw   = (gridDim.x*blockDim.x) >> 5;
    for (int r = wid; r < nrows; r += nw){
        float v1 = in[r*64 + lane], v2 = in[r*64 + lane + 32];
        if (dorelu){
            v1 = fmaxf(v1, 0.f); v2 = fmaxf(v2, 0.f);
            in[r*64 + lane] = v1; in[r*64 + lane + 32] = v2;
        }
        float s = v1*__ldg(w1+lane) + v2*__ldg(w1+lane+32);
        #pragma unroll
        for (int o = 16; o > 0; o >>= 1) s += __shfl_xor_sync(0xffffffffu, s, o);
        if (lane == 0) o1[r] = s;
    }
}

// ---------------- mixed = 0.5(a+b); ndot = mixed·w ----------------
__global__ void k_mixdot(float* __restrict__ mixed, float* __restrict__ ndot,
                         const float* __restrict__ a, const float* __restrict__ b,
                         const float* __restrict__ w, int nrows)
{
    int wid  = (blockIdx.x*blockDim.x + threadIdx.x) >> 5;
    int lane = threadIdx.x & 31;
    int nw   = (gridDim.x*blockDim.x) >> 5;
    for (int r = wid; r < nrows; r += nw){
        float v1 = 0.5f*(a[r*64 + lane]      + b[r*64 + lane]);
        float v2 = 0.5f*(a[r*64 + lane + 32] + b[r*64 + lane + 32]);
        mixed[r*64 + lane] = v1; mixed[r*64 + lane + 32] = v2;
        float s = v1*__ldg(w+lane) + v2*__ldg(w+lane+32);
        #pragma unroll
        for (int o = 16; o > 0; o >>= 1) s += __shfl_xor_sync(0xffffffffu, s, o);
        if (lane == 0) ndot[r] = s;
    }
}

__global__ void k_final(const float* __restrict__ gout, const float* __restrict__ w,
                        const float* __restrict__ b, float* __restrict__ out, int n)
{
    int wid  = (blockIdx.x*blockDim.x + threadIdx.x) >> 5;
    int lane = threadIdx.x & 31;
    if (wid >= n) return;
    float s = gout[wid*64 + lane]*__ldg(w + lane) + gout[wid*64 + lane + 32]*__ldg(w + lane + 32);
    #pragma unroll
    for (int o = 16; o > 0; o >>= 1) s += __shfl_xor_sync(0xffffffffu, s, o);
    if (lane == 0) out[wid] = s + __ldg(b);
}

// =====================================================================
extern "C" void kernel_launch(void* const* d_in, const int* in_sizes, int n_in,
                              void* d_out_, int out_size)
{
    const float* raw           = (const float*)d_in[0];
    const int*   ei            = (const int*)  d_in[1];
    const float* eattr         = (const float*)d_in[2];
    const int*   batch         = (const int*)  d_in[3];
    const float* lin1_w        = (const float*)d_in[4];
    const float* lin1_b        = (const float*)d_in[5];
    const float* gate_nl_w     = (const float*)d_in[6];
    const float* gate_nl_b     = (const float*)d_in[7];
    const float* gate_align_w  = (const float*)d_in[8];
    const float* gate_align_b  = (const float*)d_in[9];
    const float* gate_attend_w = (const float*)d_in[10];
    const float* gate_attend_b = (const float*)d_in[11];
    const float* conv_align_w  = (const float*)d_in[12];
    const float* conv_align_b  = (const float*)d_in[13];
    const float* conv_attend_w = (const float*)d_in[14];
    const float* conv_attend_b = (const float*)d_in[15];
    const float* agru_wih      = (const float*)d_in[16];
    const float* agru_whh      = (const float*)d_in[17];
    const float* agru_bih      = (const float*)d_in[18];
    const float* agru_bhh      = (const float*)d_in[19];
    const float* mol_align_w   = (const float*)d_in[20];
    const float* mol_align_b   = (const float*)d_in[21];
    const float* mol_attend_w  = (const float*)d_in[22];
    const float* mol_attend_b  = (const float*)d_in[23];
    const float* mgru_wih      = (const float*)d_in[24];
    const float* mgru_whh      = (const float*)d_in[25];
    const float* mgru_bih      = (const float*)d_in[26];
    const float* mgru_bhh      = (const float*)d_in[27];
    const float* lin2_w        = (const float*)d_in[28];
    const float* lin2_b        = (const float*)d_in[29];
    float* outp = (float*)d_out_;

    float *px, *pxl1, *ph, *pp, *pmixed, *pdots, *ppan2, *paccd, *pgout, *pmol, *pgdot, *phg;
    cudaGetSymbolAddress((void**)&px,     g_x);
    cudaGetSymbolAddress((void**)&pxl1,   g_xl1);
    cudaGetSymbolAddress((void**)&ph,     g_h);
    cudaGetSymbolAddress((void**)&pp,     g_p);
    cudaGetSymbolAddress((void**)&pmixed, g_mixed);
    cudaGetSymbolAddress((void**)&pdots,  g_dots);
    cudaGetSymbolAddress((void**)&ppan2,  g_pan2);
    cudaGetSymbolAddress((void**)&paccd,  g_accd);
    cudaGetSymbolAddress((void**)&pgout,  g_gout);
    cudaGetSymbolAddress((void**)&pmol,   g_molaccd);
    cudaGetSymbolAddress((void**)&pgdot,  g_gdot);
    cudaGetSymbolAddress((void**)&phg,    g_hg);

    float* pai    = pdots;
    float* pan    = pdots + NN;
    float* pacc   = paccd;
    float* pdenom = paccd + NN*64;
    float* paccG  = pmol;
    float* pdenG  = pmol + GG*64;

    const int GRU_SMEM = (4*32*BLD + 4*64*AHLD) * 4;
    cudaFuncSetAttribute(k_gru, cudaFuncAttributeMaxDynamicSharedMemorySize, GRU_SMEM);

    const int NT  = (NN + 63) / 64;
    const int GT  = (GG + 63) / 64;
    const int MMG = NT < 592 ? NT : 592;
    const int GRUG = NT < 148 ? NT : 148;
    const int GRUGG = GT < 148 ? GT : 148;

    // ---- initial zeroing ----
    cudaMemsetAsync(pdots, 0, 2*NN*sizeof(float));
    cudaMemsetAsync(ppan2, 0, NN*sizeof(float));
    cudaMemsetAsync(paccd, 0, (NN*64 + NN)*sizeof(float));
    cudaMemsetAsync(pgout, 0, GG*64*sizeof(float));
    cudaMemsetAsync(pmol,  0, (GG*64 + GG)*sizeof(float));

    // ---- projections (tensor-core) ----
    // px = leaky(raw@lin1.T + b); pai += px·gate_align_i  (si)
    k_mm<<<MMG, 256>>>(px, raw, lin1_w, 64, lin1_b, nullptr, nullptr,
                       gate_align_w, pai, NN, 1);
    // pp = raw@Wraw.T + b_nl
    k_mm<<<MMG, 256>>>(pp, raw, gate_nl_w, 80, gate_nl_b, nullptr, nullptr,
                       nullptr, nullptr, NN, 0);

    // ---- GATEConv ----
    k_gate_edge<<<2048, 256>>>(ei, eattr, pp, pai, gate_nl_w, gate_align_w, gate_align_b,
                               pacc, pdenom);
    k_mm<<<MMG, 256>>>(ph, pacc, gate_attend_w, 64, gate_attend_b, pdenom, pacc,
                       nullptr, nullptr, NN, 2);
    cudaMemsetAsync(pdots, 0, 2*NN*sizeof(float));  // for conv l=0 dots
    k_gru<<<GRUG, 256, GRU_SMEM>>>(px, nullptr, ph, px,
                                   agru_wih, agru_whh, agru_bih, agru_bhh,
                                   conv_align_w, conv_align_w + 64, pai, pan,
                                   nullptr, nullptr, NN);

    // ---- 2x GATConv ----
    for (int l = 0; l < 2; l++){
        k_conv_edge<<<2048, 256>>>(ei, px, pai, pan, conv_align_b + l, pacc, pdenom);
        k_mm<<<MMG, 256>>>(ph, pacc, conv_attend_w + l*4096, 64, conv_attend_b + l*64,
                           pdenom, pacc, nullptr, nullptr, NN, 2);
        if (l == 0){
            cudaMemsetAsync(pdots, 0, 2*NN*sizeof(float));  // for conv l=1 dots
            k_gru<<<GRUG, 256, GRU_SMEM>>>(px, pxl1, ph, px,
                                           agru_wih + 192*64, agru_whh + 192*64,
                                           agru_bih + 192,    agru_bhh + 192,
                                           conv_align_w + 128, conv_align_w + 192, pai, pan,
                                           nullptr, nullptr, NN);
        } else {
            // final GRU: also compute pan2 = x·mol_aj and segsum into pgout
            k_gru<<<GRUG, 256, GRU_SMEM>>>(px, nullptr, ph, px,
                                           agru_wih + 2*192*64, agru_whh + 2*192*64,
                                           agru_bih + 2*192,    agru_bhh + 2*192,
                                           mol_align_w + 64, nullptr, ppan2, nullptr,
                                           batch, pgout, NN);
        }
    }

    // ---- molecule readout ----
    k_dotg<<<128, 256>>>(pgdot, mol_align_w, pgout, GG, 1);   // relu(gout) in place + gdot

    // t = 0 (mixed = 0.5*(x + cached[-2]))
    k_mixdot<<<512, 256>>>(pmixed, pan, px, pxl1, mol_align_w + 64, NN);
    k_mol_edge<<<512, 256>>>(batch, pmixed, pgdot, pan, mol_align_b, paccG, pdenG);
    k_mm<<<GT, 256>>>(phg, paccG, mol_attend_w, 64, mol_attend_b, pdenG, paccG,
                      nullptr, nullptr, GG, 2);
    k_gru<<<GRUGG, 256, GRU_SMEM>>>(pgout, nullptr, phg, pgout,
                                    mgru_wih, mgru_whh, mgru_bih, mgru_bhh,
                                    nullptr, nullptr, nullptr, nullptr,
                                    nullptr, nullptr, GG);

    // t = 1 (mixed == x; ndot = pan2 from final GRU)
    k_dotg<<<128, 256>>>(pgdot, mol_align_w, pgout, GG, 0);
    k_mol_edge<<<512, 256>>>(batch, px, pgdot, ppan2, mol_align_b, paccG, pdenG);
    k_mm<<<GT, 256>>>(phg, paccG, mol_attend_w, 64, mol_attend_b, pdenG, paccG,
                      nullptr, nullptr, GG, 2);
    k_gru<<<GRUGG, 256, GRU_SMEM>>>(pgout, nullptr, phg, pgout,
                                    mgru_wih, mgru_whh, mgru_bih, mgru_bhh,
                                    nullptr, nullptr, nullptr, nullptr,
                                    nullptr, nullptr, GG);

    k_final<<<(GG*32 + 255)/256, 256>>>(pgout, lin2_w, lin2_b, outp, GG);
}